// round 12
// baseline (speedup 1.0000x reference)
#include <cuda_runtime.h>
#include <cuda_fp16.h>
#include <math.h>
#include <stdint.h>

#define CB 2
#define CS 2048
#define CD 1024
#define CH 16
#define CDK 64
#define CM (CB*CS)   // 4096

// ---------------------------------------------------------------------------
// Scratch (__device__ globals; allocation-free rule)
// ---------------------------------------------------------------------------
__device__ float g_trig[CS*32*2];
__device__ __half g_x16[CM*CD];
__device__ __half g_w16[4][CD*CD];          // W^T fp16 (q,k,v,o)
__device__ __half g_q16[CB*CH*CS*CDK];
__device__ __half g_k16[CB*CH*CS*CDK];
__device__ __half g_v16[CB*CH*CS*CDK];
__device__ __half g_a16[CM*CD];             // attn out fp16

// ---------------------------------------------------------------------------
// Helpers
// ---------------------------------------------------------------------------
__device__ __forceinline__ uint32_t smem_u32(const void* p) {
    uint32_t a;
    asm("{ .reg .u64 t; cvta.to.shared.u64 t, %1; cvt.u32.u64 %0, t; }" : "=r"(a) : "l"(p));
    return a;
}

__device__ __forceinline__ float ex2(float x)
{
    float r;
    asm("ex2.approx.f32 %0, %1;" : "=f"(r) : "f"(x));
    return r;
}

__device__ __forceinline__ void cpa16(uint32_t s, const void* g)
{
    asm volatile("cp.async.cg.shared.global [%0], [%1], 16;"
                 :: "r"(s), "l"(__cvta_generic_to_global(g)) : "memory");
}

__device__ __forceinline__ void ldsm4(uint32_t* r, uint32_t addr)
{
    asm volatile("ldmatrix.sync.aligned.m8n8.x4.shared.b16 {%0,%1,%2,%3}, [%4];"
                 : "=r"(r[0]), "=r"(r[1]), "=r"(r[2]), "=r"(r[3]) : "r"(addr));
}

__device__ __forceinline__ void ldsm4t(uint32_t* r, uint32_t addr)
{
    asm volatile("ldmatrix.sync.aligned.m8n8.x4.trans.shared.b16 {%0,%1,%2,%3}, [%4];"
                 : "=r"(r[0]), "=r"(r[1]), "=r"(r[2]), "=r"(r[3]) : "r"(addr));
}

__device__ __forceinline__ void mma_f16(float* c, const uint32_t* a, const uint32_t* b)
{
    asm volatile("mma.sync.aligned.m16n8k16.row.col.f32.f16.f16.f32 "
                 "{%0,%1,%2,%3}, {%4,%5,%6,%7}, {%8,%9}, {%0,%1,%2,%3};"
                 : "+f"(c[0]), "+f"(c[1]), "+f"(c[2]), "+f"(c[3])
                 : "r"(a[0]), "r"(a[1]), "r"(a[2]), "r"(a[3]), "r"(b[0]), "r"(b[1]));
}

__device__ __forceinline__ uint32_t packh2(float a, float b)
{
    __half2 t = __floats2half2_rn(a, b);
    return *(uint32_t*)&t;
}

// ---------------------------------------------------------------------------
// Fused prep kernel: blocks [0,4096) x->fp16 cvt; [4096,8192) W transpose+cvt;
// [8192,8448) trig table.
// ---------------------------------------------------------------------------
__global__ void prep_kernel(const float* __restrict__ x,
                            const float* __restrict__ W0, const float* __restrict__ W1,
                            const float* __restrict__ W2, const float* __restrict__ W3,
                            __half* __restrict__ x16, __half* __restrict__ w16)
{
    __shared__ float t[32][33];
    int bid = blockIdx.x;
    if (bid < 4096) {
        int i = (bid * 256 + threadIdx.x) * 4;
        float4 v = *(const float4*)(x + i);
        *(__half2*)(x16 + i)     = __floats2half2_rn(v.x, v.y);
        *(__half2*)(x16 + i + 2) = __floats2half2_rn(v.z, v.w);
    } else if (bid < 8192) {
        int idx = bid - 4096;
        int z = idx >> 10;
        int r = idx & 1023;
        const float* W = (z == 0) ? W0 : (z == 1) ? W1 : (z == 2) ? W2 : W3;
        __half* dst = w16 + (size_t)z * CD * CD;
        int bx = (r & 31) * 32, by = (r >> 5) * 32;
        int tx = threadIdx.x & 31, ty = threadIdx.x >> 5;
        #pragma unroll
        for (int i = 0; i < 4; i++)
            t[ty + 8*i][tx] = W[(size_t)(by + ty + 8*i) * CD + bx + tx];
        __syncthreads();
        #pragma unroll
        for (int i = 0; i < 4; i++) {
            float v = t[tx][ty + 8*i];    // = W[by+tx][bx+ty+8i]
            dst[(size_t)(bx + ty + 8*i) * CD + by + tx] = __float2half_rn(v);
        }
    } else {
        int tt = (bid - 8192) * 256 + threadIdx.x;   // 0..65535
        int s = tt >> 5, i = tt & 31;
        double theta = exp((double)i * (-log(10000.0) / 32.0));
        double a = (double)s * theta;
        g_trig[tt*2]   = (float)cos(a);
        g_trig[tt*2+1] = (float)sin(a);
    }
}

// ---------------------------------------------------------------------------
// fp16 tensor-core GEMM: C[4096,1024] = A[M,K] @ B[N,K]^T + bias  (R9 proven)
// ---------------------------------------------------------------------------
#define ASTRIDE 144
#define MATB (128*144)          // 18432
#define BUFB (2*MATB)           // A, B
#define NSTAGE 2
#define GEMM_SMEM (NSTAGE*BUFB) // 73728

struct GArgs {
    const __half *A, *B;
    int m0, n0, tid;
    uint32_t s0;
};

__device__ __forceinline__ void issue_chunk(const GArgs& a, int chunk)
{
    int k0 = chunk << 6;
    uint32_t base = a.s0 + (chunk & 1) * BUFB;
    #pragma unroll
    for (int it = 0; it < 4; it++) {
        int c = a.tid + (it << 8);
        int row = c >> 3, seg = c & 7;
        uint32_t so = row * ASTRIDE + (seg << 4);
        cpa16(base        + so, a.A + (size_t)(a.m0 + row) * CD + k0 + (seg << 3));
        cpa16(base + MATB + so, a.B + (size_t)(a.n0 + row) * CD + k0 + (seg << 3));
    }
    asm volatile("cp.async.commit_group;" ::: "memory");
}

__device__ __forceinline__ void gemm_mainloop(const GArgs& ga, float acc[2][8][4],
                                              int wm, int wn, int lane)
{
    issue_chunk(ga, 0);

    const uint32_t a_off = (wm*32 + (lane & 15)) * ASTRIDE + ((lane >> 4) << 4);
    const uint32_t b_off = MATB +
        (wn*64 + (lane & 7) + ((lane >> 4) << 3)) * ASTRIDE + (((lane >> 3) & 1) << 4);

    for (int i = 0; i < 16; i++) {
        if (i + 1 < 16) {
            issue_chunk(ga, i + 1);
            asm volatile("cp.async.wait_group 1;" ::: "memory");
        } else {
            asm volatile("cp.async.wait_group 0;" ::: "memory");
        }
        __syncthreads();

        uint32_t buf = ga.s0 + (i & 1) * BUFB;
        #pragma unroll
        for (int ks = 0; ks < 4; ks++) {
            uint32_t af[2][4], bfa[4][4];
            ldsm4(af[0], buf + a_off + ks*32);
            ldsm4(af[1], buf + a_off + 16*ASTRIDE + ks*32);
            ldsm4(bfa[0], buf + b_off                 + ks*32);
            ldsm4(bfa[1], buf + b_off + 16*ASTRIDE    + ks*32);
            ldsm4(bfa[2], buf + b_off + 32*ASTRIDE    + ks*32);
            ldsm4(bfa[3], buf + b_off + 48*ASTRIDE    + ks*32);
            #pragma unroll
            for (int tp = 0; tp < 4; tp++) {
                #pragma unroll
                for (int half = 0; half < 2; half++) {
                    int tn = tp*2 + half;
                    mma_f16(acc[0][tn], af[0], bfa[tp] + half*2);
                    mma_f16(acc[1][tn], af[1], bfa[tp] + half*2);
                }
            }
        }
        __syncthreads();
    }
}

// QKV fused; epilogue: bias, rope (q,k), q-prescale log2e/8, fp16 scatter [B,H,S,DK]
__global__ __launch_bounds__(256, 2)
void gemm_qkv(const __half* __restrict__ A, const __half* __restrict__ W16,
              const float* __restrict__ bq, const float* __restrict__ bk,
              const float* __restrict__ bv,
              __half* __restrict__ Q, __half* __restrict__ K, __half* __restrict__ V)
{
    extern __shared__ char smem[];
    const uint32_t s0 = smem_u32(smem);
    const int tid = threadIdx.x, wid = tid >> 5, lane = tid & 31;
    const int wm = wid & 3, wn = wid >> 2;
    const int m0 = blockIdx.y << 7, n0 = blockIdx.x << 7;
    const int z  = blockIdx.z;

    const __half* B = W16 + (size_t)z * CD * CD;
    const float* bias = (z == 0) ? bq : (z == 1) ? bk : bv;
    __half* D = (z == 0) ? Q : (z == 1) ? K : V;
    const bool rope = (z < 2);
    // q pre-scaled by log2(e)/sqrt(64) so softmax can use exp2
    const float oscale = (z == 0) ? 0.18033688011112042f : 1.0f;

    GArgs ga{A, B, m0, n0, tid, s0};

    float acc[2][8][4];
    #pragma unroll
    for (int i = 0; i < 2; i++)
        #pragma unroll
        for (int j = 0; j < 8; j++)
            #pragma unroll
            for (int r = 0; r < 4; r++) acc[i][j][r] = 0.f;

    gemm_mainloop(ga, acc, wm, wn, lane);

    #pragma unroll
    for (int tm = 0; tm < 2; tm++) {
        #pragma unroll
        for (int tn = 0; tn < 8; tn++) {
            int col = n0 + wn*64 + tn*8 + (lane & 3)*2;
            float b0 = bias[col], b1 = bias[col+1];
            acc[tm][tn][0] += b0; acc[tm][tn][1] += b1;
            acc[tm][tn][2] += b0; acc[tm][tn][3] += b1;
        }
    }

    if (rope) {
        #pragma unroll
        for (int tm = 0; tm < 2; tm++) {
            #pragma unroll
            for (int tn = 0; tn < 4; tn++) {
                #pragma unroll
                for (int r = 0; r < 4; r++) {
                    int row = m0 + wm*32 + tm*16 + (lane >> 2) + (r >> 1)*8;
                    int s   = row & (CS - 1);
                    int p   = tn*8 + (lane & 3)*2 + (r & 1);
                    float cc = g_trig[(s*32 + p)*2];
                    float sn = g_trig[(s*32 + p)*2 + 1];
                    float lo = acc[tm][tn][r], hi = acc[tm][tn+4][r];
                    acc[tm][tn][r]   = lo*cc - hi*sn;
                    acc[tm][tn+4][r] = hi*cc + lo*sn;
                }
            }
        }
    }

    #pragma unroll
    for (int tm = 0; tm < 2; tm++) {
        #pragma unroll
        for (int tn = 0; tn < 8; tn++) {
            int col = n0 + wn*64 + tn*8 + (lane & 3)*2;
            int h_ = col >> 6, dk = col & 63;
            #pragma unroll
            for (int rh = 0; rh < 2; rh++) {
                int row = m0 + wm*32 + tm*16 + (lane >> 2) + rh*8;
                int b_ = row >> 11, s_ = row & (CS - 1);
                size_t idx = ((size_t)((b_*CH + h_)*CS + s_)) * CDK + dk;
                *(__half2*)(D + idx) = __floats2half2_rn(acc[tm][tn][rh*2]   * oscale,
                                                         acc[tm][tn][rh*2+1] * oscale);
            }
        }
    }
}

// Output projection: row-major fp32 C.
__global__ __launch_bounds__(256, 2)
void gemm_o(const __half* __restrict__ A, const __half* __restrict__ B,
            const float* __restrict__ bias, float* __restrict__ C)
{
    extern __shared__ char smem[];
    const uint32_t s0 = smem_u32(smem);
    const int tid = threadIdx.x, wid = tid >> 5, lane = tid & 31;
    const int wm = wid & 3, wn = wid >> 2;
    const int m0 = blockIdx.y << 7, n0 = blockIdx.x << 7;

    GArgs ga{A, B, m0, n0, tid, s0};

    float acc[2][8][4];
    #pragma unroll
    for (int i = 0; i < 2; i++)
        #pragma unroll
        for (int j = 0; j < 8; j++)
            #pragma unroll
            for (int r = 0; r < 4; r++) acc[i][j][r] = 0.f;

    gemm_mainloop(ga, acc, wm, wn, lane);

    #pragma unroll
    for (int tm = 0; tm < 2; tm++) {
        #pragma unroll
        for (int tn = 0; tn < 8; tn++) {
            int col = n0 + wn*64 + tn*8 + (lane & 3)*2;
            float b0 = bias[col], b1 = bias[col+1];
            #pragma unroll
            for (int rh = 0; rh < 2; rh++) {
                int row = m0 + wm*32 + tm*16 + (lane >> 2) + rh*8;
                float* dst = C + (size_t)row * CD + col;
                *(float2*)dst = make_float2(acc[tm][tn][rh*2] + b0,
                                            acc[tm][tn][rh*2+1] + b1);
            }
        }
    }
}

// ---------------------------------------------------------------------------
// fp16 tensor-core causal flash attention (mma.sync)
// CTA: (b, h, 64-row q-tile), 128 threads = 4 warps x 16 rows.
// KV tiles of 64, double-buffered. 4 CTAs/SM. Softmax in exp2 domain.
// Diagonal tile: warp w skips fully-masked np blocks (np > w).
// ---------------------------------------------------------------------------
#define AT_STRIDE 144
#define AT_QMAT (64*AT_STRIDE)      // 9216
#define AT_KMAT (64*AT_STRIDE)      // 9216
#define AT_STAGE (2*AT_KMAT)        // 18432 (K, V)
#define ATTN_SMEM (AT_QMAT + 2*AT_STAGE)   // 46080

__global__ __launch_bounds__(128, 4)
void attn_tc(const __half* __restrict__ Qg, const __half* __restrict__ Kg,
             const __half* __restrict__ Vg, __half* __restrict__ Og)
{
    extern __shared__ char smem[];
    const uint32_t s0 = smem_u32(smem);
    const int tid = threadIdx.x, w = tid >> 5, lane = tid & 31;

    const int qt = gridDim.x - 1 - blockIdx.x;        // heavy tiles first
    const int h  = blockIdx.y, b = blockIdx.z;
    const size_t g = (size_t)(b * CH + h) * CS * CDK;
    const int q0 = qt * 64;
    const int njt = qt + 1;

    const __half *Q = Qg + g, *K = Kg + g, *V = Vg + g;

    const uint32_t sQ  = s0;
    const uint32_t sKV = s0 + AT_QMAT;

    auto issue_kv = [&](int jt) {
        int kv0 = jt * 64;
        uint32_t sb = sKV + (jt & 1) * AT_STAGE;
        #pragma unroll
        for (int it = 0; it < 4; it++) {
            int c = tid + (it << 7);
            int row = c >> 3, seg = c & 7;
            uint32_t so = row * AT_STRIDE + (seg << 4);
            size_t off = (size_t)(kv0 + row) * CDK + (seg << 3);
            cpa16(sb           + so, K + off);
            cpa16(sb + AT_KMAT + so, V + off);
        }
        asm volatile("cp.async.commit_group;" ::: "memory");
    };

    // Q load (64 rows; grouped with kv tile 0)
    #pragma unroll
    for (int it = 0; it < 4; it++) {
        int c = tid + (it << 7);
        int row = c >> 3, seg = c & 7;
        cpa16(sQ + row * AT_STRIDE + (seg << 4), Q + (size_t)(q0 + row) * CDK + (seg << 3));
    }
    issue_kv(0);
    if (njt > 1) issue_kv(1);

    const uint32_t q_off = (w*16 + (lane & 15)) * AT_STRIDE + ((lane >> 4) << 4);
    const uint32_t k_pat = ((lane & 7) + ((lane >> 4) << 3)) * AT_STRIDE + (((lane >> 3) & 1) << 4);
    const uint32_t v_pat = ((lane & 7) + (((lane >> 3) & 1) << 3)) * AT_STRIDE + ((lane >> 4) << 4);

    uint32_t qf[4][4];
    float o[8][4];
    #pragma unroll
    for (int j = 0; j < 8; j++)
        #pragma unroll
        for (int r = 0; r < 4; r++) o[j][r] = 0.f;
    float mA = -1e30f, mB = -1e30f, lA = 0.f, lB = 0.f;

    const int rowA_g = q0 + w*16 + (lane >> 2);
    const int colL   = (lane & 3) * 2;

    for (int jt = 0; jt < njt; jt++) {
        if (jt + 1 < njt) asm volatile("cp.async.wait_group 1;" ::: "memory");
        else              asm volatile("cp.async.wait_group 0;" ::: "memory");
        __syncthreads();

        if (jt == 0) {
            #pragma unroll
            for (int kc = 0; kc < 4; kc++)
                ldsm4(qf[kc], sQ + q_off + kc*32);
        }

        const uint32_t sb = sKV + (jt & 1) * AT_STAGE;
        const int kv0 = jt * 64;
        const bool diag = (jt == njt - 1);   // jt == qt

        // ---- S = Q K^T (diagonal tile: skip fully-masked np blocks) ----
        float s[8][4];
        #pragma unroll
        for (int j = 0; j < 8; j++)
            #pragma unroll
            for (int r = 0; r < 4; r++) s[j][r] = 0.f;

        #pragma unroll
        for (int kc = 0; kc < 4; kc++) {
            #pragma unroll
            for (int np = 0; np < 4; np++) {
                if (!diag || np <= w) {
                    uint32_t kf4[4];
                    ldsm4(kf4, sb + k_pat + np*16*AT_STRIDE + kc*32);
                    mma_f16(s[np*2],   qf[kc], kf4);
                    mma_f16(s[np*2+1], qf[kc], kf4 + 2);
                }
            }
        }

        // ---- mask (diagonal tile) + online softmax (exp2 domain) ----
        if (diag) {
            #pragma unroll
            for (int tn = 0; tn < 8; tn++) {
                int col = kv0 + tn*8 + colL;
                if (col     > rowA_g) s[tn][0] = -1e30f;
                if (col + 1 > rowA_g) s[tn][1] = -1e30f;
                if (col     > rowA_g + 8) s[tn][2] = -1e30f;
                if (col + 1 > rowA_g + 8) s[tn][3] = -1e30f;
            }
        }

        float mxA = -1e30f, mxB = -1e30f;
        #pragma unroll
        for (int tn = 0; tn < 8; tn++) {
            mxA = fmaxf(mxA, fmaxf(s[tn][0], s[tn][1]));
            mxB = fmaxf(mxB, fmaxf(s[tn][2], s[tn][3]));
        }
        mxA = fmaxf(mxA, __shfl_xor_sync(0xffffffffu, mxA, 1));
        mxA = fmaxf(mxA, __shfl_xor_sync(0xffffffffu, mxA, 2));
        mxB = fmaxf(mxB, __shfl_xor_sync(0xffffffffu, mxB, 1));
        mxB = fmaxf(mxB, __shfl_xor_sync(0xffffffffu, mxB, 2));

        float nmA = fmaxf(mA, mxA), nmB = fmaxf(mB, mxB);
        float facA = ex2(mA - nmA), facB = ex2(mB - nmB);

        float sumA = 0.f, sumB = 0.f;
        #pragma unroll
        for (int tn = 0; tn < 8; tn++) {
            s[tn][0] = ex2(s[tn][0] - nmA);
            s[tn][1] = ex2(s[tn][1] - nmA);
            s[tn][2] = ex2(s[tn][2] - nmB);
            s[tn][3] = ex2(s[tn][3] - nmB);
            sumA += s[tn][0] + s[tn][1];
            sumB += s[tn][2] + s[tn][3];
        }
        sumA += __shfl_xor_sync(0xffffffffu, sumA, 1);
        sumA += __shfl_xor_sync(0xffffffffu, sumA, 2);
        sumB += __shfl_xor_sync(0xffffffffu, sumB, 1);
        sumB += __shfl_xor_sync(0xffffffffu, sumB, 2);

        lA = lA*facA + sumA;  mA = nmA;
        lB = lB*facB + sumB;  mB = nmB;

        #pragma unroll
        for (int tn = 0; tn < 8; tn++) {
            o[tn][0] *= facA; o[tn][1] *= facA;
            o[tn][2] *= facB; o[tn][3] *= facB;
        }

        // ---- O += P V ----
        #pragma unroll
        for (int kc = 0; kc < 4; kc++) {
            uint32_t pa[4];
            pa[0] = packh2(s[2*kc][0],   s[2*kc][1]);
            pa[1] = packh2(s[2*kc][2],   s[2*kc][3]);
            pa[2] = packh2(s[2*kc+1][0], s[2*kc+1][1]);
            pa[3] = packh2(s[2*kc+1][2], s[2*kc+1][3]);
            uint32_t vfa[4][4];
            ldsm4t(vfa[0], sb + AT_KMAT + v_pat + kc*16*AT_STRIDE);
            ldsm4t(vfa[1], sb + AT_KMAT + v_pat + kc*16*AT_STRIDE + 32);
            ldsm4t(vfa[2], sb + AT_KMAT + v_pat + kc*16*AT_STRIDE + 64);
            ldsm4t(vfa[3], sb + AT_KMAT + v_pat + kc*16*AT_STRIDE + 96);
            #pragma unroll
            for (int np = 0; np < 4; np++) {
                mma_f16(o[np*2],   pa, vfa[np]);
                mma_f16(o[np*2+1], pa, vfa[np] + 2);
            }
        }

        __syncthreads();
        if (jt + 2 < njt) issue_kv(jt + 2);
    }

    // ---- epilogue: normalize, fp16 store to [B,S,D] ----
    float invA = 1.f / lA, invB = 1.f / lB;
    #pragma unroll
    for (int tn = 0; tn < 8; tn++) {
        int col = h*CDK + tn*8 + colL;
        #pragma unroll
        for (int rh = 0; rh < 2; rh++) {
            int q = q0 + w*16 + (lane >> 2) + rh*8;
            float inv = rh ? invB : invA;
            size_t idx = (size_t)(b*CS + q) * CD + col;
            *(__half2*)(Og + idx) = __floats2half2_rn(o[tn][rh*2] * inv,
                                                      o[tn][rh*2+1] * inv);
        }
    }
}

// ---------------------------------------------------------------------------
extern "C" void kernel_launch(void* const* d_in, const int* in_sizes, int n_in,
                              void* d_out, int out_size)
{
    const float* x  = (const float*)d_in[0];
    // d_in[1] = mask (causal triu(k=1), handled analytically)
    const float* Wq = (const float*)d_in[2];
    const float* bq = (const float*)d_in[3];
    const float* Wk = (const float*)d_in[4];
    const float* bk = (const float*)d_in[5];
    const float* Wv = (const float*)d_in[6];
    const float* bv = (const float*)d_in[7];
    const float* Wo = (const float*)d_in[8];
    const float* bo = (const float*)d_in[9];
    float* out = (float*)d_out;

    __half *x16, *w16, *q16, *k16, *v16, *a16;
    cudaGetSymbolAddress((void**)&x16, g_x16);
    cudaGetSymbolAddress((void**)&w16, g_w16);
    cudaGetSymbolAddress((void**)&q16, g_q16);
    cudaGetSymbolAddress((void**)&k16, g_k16);
    cudaGetSymbolAddress((void**)&v16, g_v16);
    cudaGetSymbolAddress((void**)&a16, g_a16);

    cudaFuncSetAttribute(attn_tc,  cudaFuncAttributeMaxDynamicSharedMemorySize, ATTN_SMEM);
    cudaFuncSetAttribute(gemm_qkv, cudaFuncAttributeMaxDynamicSharedMemorySize, GEMM_SMEM);
    cudaFuncSetAttribute(gemm_o,   cudaFuncAttributeMaxDynamicSharedMemorySize, GEMM_SMEM);

    prep_kernel<<<8448, 256>>>(x, Wq, Wk, Wv, Wo, x16, w16);

    gemm_qkv<<<dim3(CD/128, CM/128, 3), 256, GEMM_SMEM>>>(
        x16, w16, bq, bk, bv, q16, k16, v16);

    attn_tc<<<dim3(CS/64, CH, CB), 128, ATTN_SMEM>>>(q16, k16, v16, a16);

    gemm_o<<<dim3(CD/128, CM/128), 256, GEMM_SMEM>>>(
        a16, w16 + 3*(size_t)CD*CD, bo, out);
}

// round 13
// speedup vs baseline: 1.0687x; 1.0687x over previous
#include <cuda_runtime.h>
#include <cuda_fp16.h>
#include <math.h>
#include <stdint.h>

#define CB 2
#define CS 2048
#define CD 1024
#define CH 16
#define CDK 64
#define CM (CB*CS)   // 4096

// ---------------------------------------------------------------------------
// Scratch (__device__ globals; allocation-free rule)
// ---------------------------------------------------------------------------
__device__ float g_trig[CS*32*2];
__device__ __half g_x16[CM*CD];
__device__ __half g_w16[4][CD*CD];          // W^T fp16 (q,k,v,o)
__device__ __half g_q16[CB*CH*CS*CDK];
__device__ __half g_k16[CB*CH*CS*CDK];
__device__ __half g_v16[CB*CH*CS*CDK];
__device__ __half g_a16[CM*CD];             // attn out fp16

// ---------------------------------------------------------------------------
// Helpers
// ---------------------------------------------------------------------------
__device__ __forceinline__ uint32_t smem_u32(const void* p) {
    uint32_t a;
    asm("{ .reg .u64 t; cvta.to.shared.u64 t, %1; cvt.u32.u64 %0, t; }" : "=r"(a) : "l"(p));
    return a;
}

__device__ __forceinline__ float ex2(float x)
{
    float r;
    asm("ex2.approx.f32 %0, %1;" : "=f"(r) : "f"(x));
    return r;
}

__device__ __forceinline__ void cpa16(uint32_t s, const void* g)
{
    asm volatile("cp.async.cg.shared.global [%0], [%1], 16;"
                 :: "r"(s), "l"(__cvta_generic_to_global(g)) : "memory");
}

__device__ __forceinline__ void ldsm4(uint32_t* r, uint32_t addr)
{
    asm volatile("ldmatrix.sync.aligned.m8n8.x4.shared.b16 {%0,%1,%2,%3}, [%4];"
                 : "=r"(r[0]), "=r"(r[1]), "=r"(r[2]), "=r"(r[3]) : "r"(addr));
}

__device__ __forceinline__ void ldsm4t(uint32_t* r, uint32_t addr)
{
    asm volatile("ldmatrix.sync.aligned.m8n8.x4.trans.shared.b16 {%0,%1,%2,%3}, [%4];"
                 : "=r"(r[0]), "=r"(r[1]), "=r"(r[2]), "=r"(r[3]) : "r"(addr));
}

__device__ __forceinline__ void mma_f16(float* c, const uint32_t* a, const uint32_t* b)
{
    asm volatile("mma.sync.aligned.m16n8k16.row.col.f32.f16.f16.f32 "
                 "{%0,%1,%2,%3}, {%4,%5,%6,%7}, {%8,%9}, {%0,%1,%2,%3};"
                 : "+f"(c[0]), "+f"(c[1]), "+f"(c[2]), "+f"(c[3])
                 : "r"(a[0]), "r"(a[1]), "r"(a[2]), "r"(a[3]), "r"(b[0]), "r"(b[1]));
}

__device__ __forceinline__ uint32_t packh2(float a, float b)
{
    __half2 t = __floats2half2_rn(a, b);
    return *(uint32_t*)&t;
}

// ---------------------------------------------------------------------------
// Prep kernels
// ---------------------------------------------------------------------------
__global__ void trig_kernel()
{
    int t = blockIdx.x * 256 + threadIdx.x;
    int s = t >> 5, i = t & 31;
    double theta = exp((double)i * (-log(10000.0) / 32.0));
    double a = (double)s * theta;
    g_trig[t*2]   = (float)cos(a);
    g_trig[t*2+1] = (float)sin(a);
}

__global__ void cvt_kernel(const float* __restrict__ src, __half* __restrict__ dst)
{
    int i = (blockIdx.x * 256 + threadIdx.x) * 4;
    float4 v = *(const float4*)(src + i);
    *(__half2*)(dst + i)     = __floats2half2_rn(v.x, v.y);
    *(__half2*)(dst + i + 2) = __floats2half2_rn(v.z, v.w);
}

// W[k][n] -> out[n][k] transposed fp16; z selects which of 4 weights
__global__ void wcvt_kernel(const float* __restrict__ W0, const float* __restrict__ W1,
                            const float* __restrict__ W2, const float* __restrict__ W3,
                            __half* __restrict__ out)
{
    __shared__ float t[32][33];
    const int z = blockIdx.z;
    const float* W = (z == 0) ? W0 : (z == 1) ? W1 : (z == 2) ? W2 : W3;
    __half* dst = out + (size_t)z * CD * CD;
    int bx = blockIdx.x * 32, by = blockIdx.y * 32;
    int tx = threadIdx.x & 31, ty = threadIdx.x >> 5;
    #pragma unroll
    for (int i = 0; i < 4; i++)
        t[ty + 8*i][tx] = W[(size_t)(by + ty + 8*i) * CD + bx + tx];
    __syncthreads();
    #pragma unroll
    for (int i = 0; i < 4; i++) {
        float x = t[tx][ty + 8*i];    // = W[by+tx][bx+ty+8i]
        dst[(size_t)(bx + ty + 8*i) * CD + by + tx] = __float2half_rn(x);
    }
}

// ---------------------------------------------------------------------------
// fp16 tensor-core GEMM: C[4096,1024] = A[M,K] @ B[N,K]^T + bias  (R9 proven)
// ---------------------------------------------------------------------------
#define ASTRIDE 144
#define MATB (128*144)          // 18432
#define BUFB (2*MATB)           // A, B
#define NSTAGE 2
#define GEMM_SMEM (NSTAGE*BUFB) // 73728

struct GArgs {
    const __half *A, *B;
    int m0, n0, tid;
    uint32_t s0;
};

__device__ __forceinline__ void issue_chunk(const GArgs& a, int chunk)
{
    int k0 = chunk << 6;
    uint32_t base = a.s0 + (chunk & 1) * BUFB;
    #pragma unroll
    for (int it = 0; it < 4; it++) {
        int c = a.tid + (it << 8);
        int row = c >> 3, seg = c & 7;
        uint32_t so = row * ASTRIDE + (seg << 4);
        cpa16(base        + so, a.A + (size_t)(a.m0 + row) * CD + k0 + (seg << 3));
        cpa16(base + MATB + so, a.B + (size_t)(a.n0 + row) * CD + k0 + (seg << 3));
    }
    asm volatile("cp.async.commit_group;" ::: "memory");
}

__device__ __forceinline__ void gemm_mainloop(const GArgs& ga, float acc[2][8][4],
                                              int wm, int wn, int lane)
{
    issue_chunk(ga, 0);

    const uint32_t a_off = (wm*32 + (lane & 15)) * ASTRIDE + ((lane >> 4) << 4);
    const uint32_t b_off = MATB +
        (wn*64 + (lane & 7) + ((lane >> 4) << 3)) * ASTRIDE + (((lane >> 3) & 1) << 4);

    for (int i = 0; i < 16; i++) {
        if (i + 1 < 16) {
            issue_chunk(ga, i + 1);
            asm volatile("cp.async.wait_group 1;" ::: "memory");
        } else {
            asm volatile("cp.async.wait_group 0;" ::: "memory");
        }
        __syncthreads();

        uint32_t buf = ga.s0 + (i & 1) * BUFB;
        #pragma unroll
        for (int ks = 0; ks < 4; ks++) {
            uint32_t af[2][4], bfa[4][4];
            ldsm4(af[0], buf + a_off + ks*32);
            ldsm4(af[1], buf + a_off + 16*ASTRIDE + ks*32);
            ldsm4(bfa[0], buf + b_off                 + ks*32);
            ldsm4(bfa[1], buf + b_off + 16*ASTRIDE    + ks*32);
            ldsm4(bfa[2], buf + b_off + 32*ASTRIDE    + ks*32);
            ldsm4(bfa[3], buf + b_off + 48*ASTRIDE    + ks*32);
            #pragma unroll
            for (int tp = 0; tp < 4; tp++) {
                #pragma unroll
                for (int half = 0; half < 2; half++) {
                    int tn = tp*2 + half;
                    mma_f16(acc[0][tn], af[0], bfa[tp] + half*2);
                    mma_f16(acc[1][tn], af[1], bfa[tp] + half*2);
                }
            }
        }
        __syncthreads();
    }
}

// QKV fused; epilogue: bias, rope (q,k), q-prescale log2e/8, fp16 scatter [B,H,S,DK]
__global__ __launch_bounds__(256, 2)
void gemm_qkv(const __half* __restrict__ A, const __half* __restrict__ W16,
              const float* __restrict__ bq, const float* __restrict__ bk,
              const float* __restrict__ bv,
              __half* __restrict__ Q, __half* __restrict__ K, __half* __restrict__ V)
{
    extern __shared__ char smem[];
    const uint32_t s0 = smem_u32(smem);
    const int tid = threadIdx.x, wid = tid >> 5, lane = tid & 31;
    const int wm = wid & 3, wn = wid >> 2;
    const int m0 = blockIdx.y << 7, n0 = blockIdx.x << 7;
    const int z  = blockIdx.z;

    const __half* B = W16 + (size_t)z * CD * CD;
    const float* bias = (z == 0) ? bq : (z == 1) ? bk : bv;
    __half* D = (z == 0) ? Q : (z == 1) ? K : V;
    const bool rope = (z < 2);
    // q pre-scaled by log2(e)/sqrt(64) so softmax can use exp2
    const float oscale = (z == 0) ? 0.18033688011112042f : 1.0f;

    GArgs ga{A, B, m0, n0, tid, s0};

    float acc[2][8][4];
    #pragma unroll
    for (int i = 0; i < 2; i++)
        #pragma unroll
        for (int j = 0; j < 8; j++)
            #pragma unroll
            for (int r = 0; r < 4; r++) acc[i][j][r] = 0.f;

    gemm_mainloop(ga, acc, wm, wn, lane);

    #pragma unroll
    for (int tm = 0; tm < 2; tm++) {
        #pragma unroll
        for (int tn = 0; tn < 8; tn++) {
            int col = n0 + wn*64 + tn*8 + (lane & 3)*2;
            float b0 = bias[col], b1 = bias[col+1];
            acc[tm][tn][0] += b0; acc[tm][tn][1] += b1;
            acc[tm][tn][2] += b0; acc[tm][tn][3] += b1;
        }
    }

    if (rope) {
        #pragma unroll
        for (int tm = 0; tm < 2; tm++) {
            #pragma unroll
            for (int tn = 0; tn < 4; tn++) {
                #pragma unroll
                for (int r = 0; r < 4; r++) {
                    int row = m0 + wm*32 + tm*16 + (lane >> 2) + (r >> 1)*8;
                    int s   = row & (CS - 1);
                    int p   = tn*8 + (lane & 3)*2 + (r & 1);
                    float cc = g_trig[(s*32 + p)*2];
                    float sn = g_trig[(s*32 + p)*2 + 1];
                    float lo = acc[tm][tn][r], hi = acc[tm][tn+4][r];
                    acc[tm][tn][r]   = lo*cc - hi*sn;
                    acc[tm][tn+4][r] = hi*cc + lo*sn;
                }
            }
        }
    }

    #pragma unroll
    for (int tm = 0; tm < 2; tm++) {
        #pragma unroll
        for (int tn = 0; tn < 8; tn++) {
            int col = n0 + wn*64 + tn*8 + (lane & 3)*2;
            int h_ = col >> 6, dk = col & 63;
            #pragma unroll
            for (int rh = 0; rh < 2; rh++) {
                int row = m0 + wm*32 + tm*16 + (lane >> 2) + rh*8;
                int b_ = row >> 11, s_ = row & (CS - 1);
                size_t idx = ((size_t)((b_*CH + h_)*CS + s_)) * CDK + dk;
                *(__half2*)(D + idx) = __floats2half2_rn(acc[tm][tn][rh*2]   * oscale,
                                                         acc[tm][tn][rh*2+1] * oscale);
            }
        }
    }
}

// Output projection: row-major fp32 C.
__global__ __launch_bounds__(256, 2)
void gemm_o(const __half* __restrict__ A, const __half* __restrict__ B,
            const float* __restrict__ bias, float* __restrict__ C)
{
    extern __shared__ char smem[];
    const uint32_t s0 = smem_u32(smem);
    const int tid = threadIdx.x, wid = tid >> 5, lane = tid & 31;
    const int wm = wid & 3, wn = wid >> 2;
    const int m0 = blockIdx.y << 7, n0 = blockIdx.x << 7;

    GArgs ga{A, B, m0, n0, tid, s0};

    float acc[2][8][4];
    #pragma unroll
    for (int i = 0; i < 2; i++)
        #pragma unroll
        for (int j = 0; j < 8; j++)
            #pragma unroll
            for (int r = 0; r < 4; r++) acc[i][j][r] = 0.f;

    gemm_mainloop(ga, acc, wm, wn, lane);

    #pragma unroll
    for (int tm = 0; tm < 2; tm++) {
        #pragma unroll
        for (int tn = 0; tn < 8; tn++) {
            int col = n0 + wn*64 + tn*8 + (lane & 3)*2;
            float b0 = bias[col], b1 = bias[col+1];
            #pragma unroll
            for (int rh = 0; rh < 2; rh++) {
                int row = m0 + wm*32 + tm*16 + (lane >> 2) + rh*8;
                float* dst = C + (size_t)row * CD + col;
                *(float2*)dst = make_float2(acc[tm][tn][rh*2] + b0,
                                            acc[tm][tn][rh*2+1] + b1);
            }
        }
    }
}

// ---------------------------------------------------------------------------
// fp16 tensor-core causal flash attention (mma.sync)
// CTA: (b, h, 64-row q-tile), 128 threads = 4 warps x 16 rows.
// KV tiles of 64, double-buffered. 4 CTAs/SM. Softmax in exp2 domain
// (Q pre-scaled by log2e/8 in projection epilogue).
// ---------------------------------------------------------------------------
#define AT_STRIDE 144
#define AT_QMAT (64*AT_STRIDE)      // 9216
#define AT_KMAT (64*AT_STRIDE)      // 9216
#define AT_STAGE (2*AT_KMAT)        // 18432 (K, V)
#define ATTN_SMEM (AT_QMAT + 2*AT_STAGE)   // 46080

__global__ __launch_bounds__(128, 4)
void attn_tc(const __half* __restrict__ Qg, const __half* __restrict__ Kg,
             const __half* __restrict__ Vg, __half* __restrict__ Og)
{
    extern __shared__ char smem[];
    const uint32_t s0 = smem_u32(smem);
    const int tid = threadIdx.x, w = tid >> 5, lane = tid & 31;

    const int qt = gridDim.x - 1 - blockIdx.x;        // heavy tiles first
    const int h  = blockIdx.y, b = blockIdx.z;
    const size_t g = (size_t)(b * CH + h) * CS * CDK;
    const int q0 = qt * 64;
    const int njt = qt + 1;

    const __half *Q = Qg + g, *K = Kg + g, *V = Vg + g;

    const uint32_t sQ  = s0;
    const uint32_t sKV = s0 + AT_QMAT;

    auto issue_kv = [&](int jt) {
        int kv0 = jt * 64;
        uint32_t sb = sKV + (jt & 1) * AT_STAGE;
        #pragma unroll
        for (int it = 0; it < 4; it++) {       // 64 rows x 8 segs = 512 / 128 thr
            int c = tid + (it << 7);
            int row = c >> 3, seg = c & 7;
            uint32_t so = row * AT_STRIDE + (seg << 4);
            size_t off = (size_t)(kv0 + row) * CDK + (seg << 3);
            cpa16(sb           + so, K + off);
            cpa16(sb + AT_KMAT + so, V + off);
        }
        asm volatile("cp.async.commit_group;" ::: "memory");
    };

    // Q load (64 rows; grouped with kv tile 0)
    #pragma unroll
    for (int it = 0; it < 4; it++) {
        int c = tid + (it << 7);
        int row = c >> 3, seg = c & 7;
        cpa16(sQ + row * AT_STRIDE + (seg << 4), Q + (size_t)(q0 + row) * CDK + (seg << 3));
    }
    issue_kv(0);
    if (njt > 1) issue_kv(1);

    const uint32_t q_off = (w*16 + (lane & 15)) * AT_STRIDE + ((lane >> 4) << 4);
    const uint32_t k_pat = ((lane & 7) + ((lane >> 4) << 3)) * AT_STRIDE + (((lane >> 3) & 1) << 4);
    const uint32_t v_pat = ((lane & 7) + (((lane >> 3) & 1) << 3)) * AT_STRIDE + ((lane >> 4) << 4);

    uint32_t qf[4][4];
    float o[8][4];
    #pragma unroll
    for (int j = 0; j < 8; j++)
        #pragma unroll
        for (int r = 0; r < 4; r++) o[j][r] = 0.f;
    float mA = -1e30f, mB = -1e30f, lA = 0.f, lB = 0.f;

    const int rowA_g = q0 + w*16 + (lane >> 2);
    const int colL   = (lane & 3) * 2;

    for (int jt = 0; jt < njt; jt++) {
        if (jt + 1 < njt) asm volatile("cp.async.wait_group 1;" ::: "memory");
        else              asm volatile("cp.async.wait_group 0;" ::: "memory");
        __syncthreads();

        if (jt == 0) {
            #pragma unroll
            for (int kc = 0; kc < 4; kc++)
                ldsm4(qf[kc], sQ + q_off + kc*32);
        }

        const uint32_t sb = sKV + (jt & 1) * AT_STAGE;
        const int kv0 = jt * 64;

        // ---- S = Q K^T ----
        float s[8][4];
        #pragma unroll
        for (int j = 0; j < 8; j++)
            #pragma unroll
            for (int r = 0; r < 4; r++) s[j][r] = 0.f;

        #pragma unroll
        for (int kc = 0; kc < 4; kc++) {
            uint32_t kfa[4][4];
            ldsm4(kfa[0], sb + k_pat                 + kc*32);
            ldsm4(kfa[1], sb + k_pat + 16*AT_STRIDE  + kc*32);
            ldsm4(kfa[2], sb + k_pat + 32*AT_STRIDE  + kc*32);
            ldsm4(kfa[3], sb + k_pat + 48*AT_STRIDE  + kc*32);
            #pragma unroll
            for (int np = 0; np < 4; np++) {
                mma_f16(s[np*2],   qf[kc], kfa[np]);
                mma_f16(s[np*2+1], qf[kc], kfa[np] + 2);
            }
        }

        // ---- mask (diagonal tile) + online softmax (exp2 domain) ----
        if (jt == qt) {
            #pragma unroll
            for (int tn = 0; tn < 8; tn++) {
                int col = kv0 + tn*8 + colL;
                if (col     > rowA_g) s[tn][0] = -1e30f;
                if (col + 1 > rowA_g) s[tn][1] = -1e30f;
                if (col     > rowA_g + 8) s[tn][2] = -1e30f;
                if (col + 1 > rowA_g + 8) s[tn][3] = -1e30f;
            }
        }

        float mxA = -1e30f, mxB = -1e30f;
        #pragma unroll
        for (int tn = 0; tn < 8; tn++) {
            mxA = fmaxf(mxA, fmaxf(s[tn][0], s[tn][1]));
            mxB = fmaxf(mxB, fmaxf(s[tn][2], s[tn][3]));
        }
        mxA = fmaxf(mxA, __shfl_xor_sync(0xffffffffu, mxA, 1));
        mxA = fmaxf(mxA, __shfl_xor_sync(0xffffffffu, mxA, 2));
        mxB = fmaxf(mxB, __shfl_xor_sync(0xffffffffu, mxB, 1));
        mxB = fmaxf(mxB, __shfl_xor_sync(0xffffffffu, mxB, 2));

        float nmA = fmaxf(mA, mxA), nmB = fmaxf(mB, mxB);
        float facA = ex2(mA - nmA), facB = ex2(mB - nmB);

        float sumA = 0.f, sumB = 0.f;
        #pragma unroll
        for (int tn = 0; tn < 8; tn++) {
            s[tn][0] = ex2(s[tn][0] - nmA);
            s[tn][1] = ex2(s[tn][1] - nmA);
            s[tn][2] = ex2(s[tn][2] - nmB);
            s[tn][3] = ex2(s[tn][3] - nmB);
            sumA += s[tn][0] + s[tn][1];
            sumB += s[tn][2] + s[tn][3];
        }
        sumA += __shfl_xor_sync(0xffffffffu, sumA, 1);
        sumA += __shfl_xor_sync(0xffffffffu, sumA, 2);
        sumB += __shfl_xor_sync(0xffffffffu, sumB, 1);
        sumB += __shfl_xor_sync(0xffffffffu, sumB, 2);

        lA = lA*facA + sumA;  mA = nmA;
        lB = lB*facB + sumB;  mB = nmB;

        #pragma unroll
        for (int tn = 0; tn < 8; tn++) {
            o[tn][0] *= facA; o[tn][1] *= facA;
            o[tn][2] *= facB; o[tn][3] *= facB;
        }

        // ---- O += P V ----
        #pragma unroll
        for (int kc = 0; kc < 4; kc++) {
            uint32_t pa[4];
            pa[0] = packh2(s[2*kc][0],   s[2*kc][1]);
            pa[1] = packh2(s[2*kc][2],   s[2*kc][3]);
            pa[2] = packh2(s[2*kc+1][0], s[2*kc+1][1]);
            pa[3] = packh2(s[2*kc+1][2], s[2*kc+1][3]);
            uint32_t vfa[4][4];
            ldsm4t(vfa[0], sb + AT_KMAT + v_pat + kc*16*AT_STRIDE);
            ldsm4t(vfa[1], sb + AT_KMAT + v_pat + kc*16*AT_STRIDE + 32);
            ldsm4t(vfa[2], sb + AT_KMAT + v_pat + kc*16*AT_STRIDE + 64);
            ldsm4t(vfa[3], sb + AT_KMAT + v_pat + kc*16*AT_STRIDE + 96);
            #pragma unroll
            for (int np = 0; np < 4; np++) {
                mma_f16(o[np*2],   pa, vfa[np]);
                mma_f16(o[np*2+1], pa, vfa[np] + 2);
            }
        }

        __syncthreads();
        if (jt + 2 < njt) issue_kv(jt + 2);
    }

    // ---- epilogue: normalize, fp16 store to [B,S,D] ----
    float invA = 1.f / lA, invB = 1.f / lB;
    #pragma unroll
    for (int tn = 0; tn < 8; tn++) {
        int col = h*CDK + tn*8 + colL;
        #pragma unroll
        for (int rh = 0; rh < 2; rh++) {
            int q = q0 + w*16 + (lane >> 2) + rh*8;
            float inv = rh ? invB : invA;
            size_t idx = (size_t)(b*CS + q) * CD + col;
            *(__half2*)(Og + idx) = __floats2half2_rn(o[tn][rh*2] * inv,
                                                      o[tn][rh*2+1] * inv);
        }
    }
}

// ---------------------------------------------------------------------------
extern "C" void kernel_launch(void* const* d_in, const int* in_sizes, int n_in,
                              void* d_out, int out_size)
{
    const float* x  = (const float*)d_in[0];
    // d_in[1] = mask (causal triu(k=1), handled analytically)
    const float* Wq = (const float*)d_in[2];
    const float* bq = (const float*)d_in[3];
    const float* Wk = (const float*)d_in[4];
    const float* bk = (const float*)d_in[5];
    const float* Wv = (const float*)d_in[6];
    const float* bv = (const float*)d_in[7];
    const float* Wo = (const float*)d_in[8];
    const float* bo = (const float*)d_in[9];
    float* out = (float*)d_out;

    __half *x16, *w16, *q16, *k16, *v16, *a16;
    cudaGetSymbolAddress((void**)&x16, g_x16);
    cudaGetSymbolAddress((void**)&w16, g_w16);
    cudaGetSymbolAddress((void**)&q16, g_q16);
    cudaGetSymbolAddress((void**)&k16, g_k16);
    cudaGetSymbolAddress((void**)&v16, g_v16);
    cudaGetSymbolAddress((void**)&a16, g_a16);

    cudaFuncSetAttribute(attn_tc,  cudaFuncAttributeMaxDynamicSharedMemorySize, ATTN_SMEM);
    cudaFuncSetAttribute(gemm_qkv, cudaFuncAttributeMaxDynamicSharedMemorySize, GEMM_SMEM);
    cudaFuncSetAttribute(gemm_o,   cudaFuncAttributeMaxDynamicSharedMemorySize, GEMM_SMEM);

    trig_kernel<<<256, 256>>>();
    cvt_kernel<<<(CM*CD)/1024, 256>>>(x, x16);
    wcvt_kernel<<<dim3(32,32,4), 256>>>(Wq, Wk, Wv, Wo, w16);

    gemm_qkv<<<dim3(CD/128, CM/128, 3), 256, GEMM_SMEM>>>(
        x16, w16, bq, bk, bv, q16, k16, v16);

    attn_tc<<<dim3(CS/64, CH, CB), 128, ATTN_SMEM>>>(q16, k16, v16, a16);

    gemm_o<<<dim3(CD/128, CM/128), 256, GEMM_SMEM>>>(
        a16, w16 + 3*(size_t)CD*CD, bo, out);
}

// round 14
// speedup vs baseline: 1.1011x; 1.0304x over previous
#include <cuda_runtime.h>
#include <cuda_fp16.h>
#include <math.h>
#include <stdint.h>

#define CB 2
#define CS 2048
#define CD 1024
#define CH 16
#define CDK 64
#define CM (CB*CS)   // 4096

// ---------------------------------------------------------------------------
// Scratch (__device__ globals; allocation-free rule)
// ---------------------------------------------------------------------------
__device__ float g_trig[CS*32*2];
__device__ __half g_x16[CM*CD];
__device__ __half g_w16[4][CD*CD];          // W^T fp16 (q,k,v,o)
__device__ __half g_q16[CB*CH*CS*CDK];
__device__ __half g_k16[CB*CH*CS*CDK];
__device__ __half g_v16[CB*CH*CS*CDK];
__device__ __half g_a16[CM*CD];             // attn out fp16

// ---------------------------------------------------------------------------
// Helpers
// ---------------------------------------------------------------------------
__device__ __forceinline__ uint32_t smem_u32(const void* p) {
    uint32_t a;
    asm("{ .reg .u64 t; cvta.to.shared.u64 t, %1; cvt.u32.u64 %0, t; }" : "=r"(a) : "l"(p));
    return a;
}

__device__ __forceinline__ float ex2(float x)
{
    float r;
    asm("ex2.approx.f32 %0, %1;" : "=f"(r) : "f"(x));
    return r;
}

__device__ __forceinline__ void cpa16(uint32_t s, const void* g)
{
    asm volatile("cp.async.cg.shared.global [%0], [%1], 16;"
                 :: "r"(s), "l"(__cvta_generic_to_global(g)) : "memory");
}

__device__ __forceinline__ void ldsm4(uint32_t* r, uint32_t addr)
{
    asm volatile("ldmatrix.sync.aligned.m8n8.x4.shared.b16 {%0,%1,%2,%3}, [%4];"
                 : "=r"(r[0]), "=r"(r[1]), "=r"(r[2]), "=r"(r[3]) : "r"(addr));
}

__device__ __forceinline__ void ldsm4t(uint32_t* r, uint32_t addr)
{
    asm volatile("ldmatrix.sync.aligned.m8n8.x4.trans.shared.b16 {%0,%1,%2,%3}, [%4];"
                 : "=r"(r[0]), "=r"(r[1]), "=r"(r[2]), "=r"(r[3]) : "r"(addr));
}

__device__ __forceinline__ void mma_f16(float* c, const uint32_t* a, const uint32_t* b)
{
    asm volatile("mma.sync.aligned.m16n8k16.row.col.f32.f16.f16.f32 "
                 "{%0,%1,%2,%3}, {%4,%5,%6,%7}, {%8,%9}, {%0,%1,%2,%3};"
                 : "+f"(c[0]), "+f"(c[1]), "+f"(c[2]), "+f"(c[3])
                 : "r"(a[0]), "r"(a[1]), "r"(a[2]), "r"(a[3]), "r"(b[0]), "r"(b[1]));
}

__device__ __forceinline__ uint32_t packh2(float a, float b)
{
    __half2 t = __floats2half2_rn(a, b);
    return *(uint32_t*)&t;
}

// ---------------------------------------------------------------------------
// Prep kernels
// ---------------------------------------------------------------------------
__global__ void trig_kernel()
{
    int t = blockIdx.x * 256 + threadIdx.x;
    int s = t >> 5, i = t & 31;
    double theta = exp((double)i * (-log(10000.0) / 32.0));
    double a = (double)s * theta;
    g_trig[t*2]   = (float)cos(a);
    g_trig[t*2+1] = (float)sin(a);
}

__global__ void cvt_kernel(const float* __restrict__ src, __half* __restrict__ dst)
{
    int i = (blockIdx.x * 256 + threadIdx.x) * 4;
    float4 v = *(const float4*)(src + i);
    *(__half2*)(dst + i)     = __floats2half2_rn(v.x, v.y);
    *(__half2*)(dst + i + 2) = __floats2half2_rn(v.z, v.w);
}

// W[k][n] -> out[n][k] transposed fp16; z selects which of 4 weights
__global__ void wcvt_kernel(const float* __restrict__ W0, const float* __restrict__ W1,
                            const float* __restrict__ W2, const float* __restrict__ W3,
                            __half* __restrict__ out)
{
    __shared__ float t[32][33];
    const int z = blockIdx.z;
    const float* W = (z == 0) ? W0 : (z == 1) ? W1 : (z == 2) ? W2 : W3;
    __half* dst = out + (size_t)z * CD * CD;
    int bx = blockIdx.x * 32, by = blockIdx.y * 32;
    int tx = threadIdx.x & 31, ty = threadIdx.x >> 5;
    #pragma unroll
    for (int i = 0; i < 4; i++)
        t[ty + 8*i][tx] = W[(size_t)(by + ty + 8*i) * CD + bx + tx];
    __syncthreads();
    #pragma unroll
    for (int i = 0; i < 4; i++) {
        float x = t[tx][ty + 8*i];    // = W[by+tx][bx+ty+8i]
        dst[(size_t)(bx + ty + 8*i) * CD + by + tx] = __float2half_rn(x);
    }
}

// ---------------------------------------------------------------------------
// fp16 tensor-core GEMM: C[4096,1024] = A[M,K] @ B[N,K]^T + bias  (R9 proven)
// ---------------------------------------------------------------------------
#define ASTRIDE 144
#define MATB (128*144)          // 18432
#define BUFB (2*MATB)           // A, B
#define NSTAGE 2
#define GEMM_SMEM (NSTAGE*BUFB) // 73728

struct GArgs {
    const __half *A, *B;
    int m0, n0, tid;
    uint32_t s0;
};

__device__ __forceinline__ void issue_chunk(const GArgs& a, int chunk)
{
    int k0 = chunk << 6;
    uint32_t base = a.s0 + (chunk & 1) * BUFB;
    #pragma unroll
    for (int it = 0; it < 4; it++) {
        int c = a.tid + (it << 8);
        int row = c >> 3, seg = c & 7;
        uint32_t so = row * ASTRIDE + (seg << 4);
        cpa16(base        + so, a.A + (size_t)(a.m0 + row) * CD + k0 + (seg << 3));
        cpa16(base + MATB + so, a.B + (size_t)(a.n0 + row) * CD + k0 + (seg << 3));
    }
    asm volatile("cp.async.commit_group;" ::: "memory");
}

__device__ __forceinline__ void gemm_mainloop(const GArgs& ga, float acc[2][8][4],
                                              int wm, int wn, int lane)
{
    issue_chunk(ga, 0);

    const uint32_t a_off = (wm*32 + (lane & 15)) * ASTRIDE + ((lane >> 4) << 4);
    const uint32_t b_off = MATB +
        (wn*64 + (lane & 7) + ((lane >> 4) << 3)) * ASTRIDE + (((lane >> 3) & 1) << 4);

    for (int i = 0; i < 16; i++) {
        if (i + 1 < 16) {
            issue_chunk(ga, i + 1);
            asm volatile("cp.async.wait_group 1;" ::: "memory");
        } else {
            asm volatile("cp.async.wait_group 0;" ::: "memory");
        }
        __syncthreads();

        uint32_t buf = ga.s0 + (i & 1) * BUFB;
        #pragma unroll
        for (int ks = 0; ks < 4; ks++) {
            uint32_t af[2][4], bfa[4][4];
            ldsm4(af[0], buf + a_off + ks*32);
            ldsm4(af[1], buf + a_off + 16*ASTRIDE + ks*32);
            ldsm4(bfa[0], buf + b_off                 + ks*32);
            ldsm4(bfa[1], buf + b_off + 16*ASTRIDE    + ks*32);
            ldsm4(bfa[2], buf + b_off + 32*ASTRIDE    + ks*32);
            ldsm4(bfa[3], buf + b_off + 48*ASTRIDE    + ks*32);
            #pragma unroll
            for (int tp = 0; tp < 4; tp++) {
                #pragma unroll
                for (int half = 0; half < 2; half++) {
                    int tn = tp*2 + half;
                    mma_f16(acc[0][tn], af[0], bfa[tp] + half*2);
                    mma_f16(acc[1][tn], af[1], bfa[tp] + half*2);
                }
            }
        }
        __syncthreads();
    }
}

// QKV fused; epilogue: bias, rope (q,k), q-prescale log2e/8, fp16 scatter [B,H,S,DK]
__global__ __launch_bounds__(256, 2)
void gemm_qkv(const __half* __restrict__ A, const __half* __restrict__ W16,
              const float* __restrict__ bq, const float* __restrict__ bk,
              const float* __restrict__ bv,
              __half* __restrict__ Q, __half* __restrict__ K, __half* __restrict__ V)
{
    extern __shared__ char smem[];
    const uint32_t s0 = smem_u32(smem);
    const int tid = threadIdx.x, wid = tid >> 5, lane = tid & 31;
    const int wm = wid & 3, wn = wid >> 2;
    const int m0 = blockIdx.y << 7, n0 = blockIdx.x << 7;
    const int z  = blockIdx.z;

    const __half* B = W16 + (size_t)z * CD * CD;
    const float* bias = (z == 0) ? bq : (z == 1) ? bk : bv;
    __half* D = (z == 0) ? Q : (z == 1) ? K : V;
    const bool rope = (z < 2);
    // q pre-scaled by log2(e)/sqrt(64) so softmax can use exp2
    const float oscale = (z == 0) ? 0.18033688011112042f : 1.0f;

    GArgs ga{A, B, m0, n0, tid, s0};

    float acc[2][8][4];
    #pragma unroll
    for (int i = 0; i < 2; i++)
        #pragma unroll
        for (int j = 0; j < 8; j++)
            #pragma unroll
            for (int r = 0; r < 4; r++) acc[i][j][r] = 0.f;

    gemm_mainloop(ga, acc, wm, wn, lane);

    #pragma unroll
    for (int tm = 0; tm < 2; tm++) {
        #pragma unroll
        for (int tn = 0; tn < 8; tn++) {
            int col = n0 + wn*64 + tn*8 + (lane & 3)*2;
            float b0 = bias[col], b1 = bias[col+1];
            acc[tm][tn][0] += b0; acc[tm][tn][1] += b1;
            acc[tm][tn][2] += b0; acc[tm][tn][3] += b1;
        }
    }

    if (rope) {
        #pragma unroll
        for (int tm = 0; tm < 2; tm++) {
            #pragma unroll
            for (int tn = 0; tn < 4; tn++) {
                #pragma unroll
                for (int r = 0; r < 4; r++) {
                    int row = m0 + wm*32 + tm*16 + (lane >> 2) + (r >> 1)*8;
                    int s   = row & (CS - 1);
                    int p   = tn*8 + (lane & 3)*2 + (r & 1);
                    float cc = g_trig[(s*32 + p)*2];
                    float sn = g_trig[(s*32 + p)*2 + 1];
                    float lo = acc[tm][tn][r], hi = acc[tm][tn+4][r];
                    acc[tm][tn][r]   = lo*cc - hi*sn;
                    acc[tm][tn+4][r] = hi*cc + lo*sn;
                }
            }
        }
    }

    #pragma unroll
    for (int tm = 0; tm < 2; tm++) {
        #pragma unroll
        for (int tn = 0; tn < 8; tn++) {
            int col = n0 + wn*64 + tn*8 + (lane & 3)*2;
            int h_ = col >> 6, dk = col & 63;
            #pragma unroll
            for (int rh = 0; rh < 2; rh++) {
                int row = m0 + wm*32 + tm*16 + (lane >> 2) + rh*8;
                int b_ = row >> 11, s_ = row & (CS - 1);
                size_t idx = ((size_t)((b_*CH + h_)*CS + s_)) * CDK + dk;
                *(__half2*)(D + idx) = __floats2half2_rn(acc[tm][tn][rh*2]   * oscale,
                                                         acc[tm][tn][rh*2+1] * oscale);
            }
        }
    }
}

// Output projection: row-major fp32 C.
__global__ __launch_bounds__(256, 2)
void gemm_o(const __half* __restrict__ A, const __half* __restrict__ B,
            const float* __restrict__ bias, float* __restrict__ C)
{
    extern __shared__ char smem[];
    const uint32_t s0 = smem_u32(smem);
    const int tid = threadIdx.x, wid = tid >> 5, lane = tid & 31;
    const int wm = wid & 3, wn = wid >> 2;
    const int m0 = blockIdx.y << 7, n0 = blockIdx.x << 7;

    GArgs ga{A, B, m0, n0, tid, s0};

    float acc[2][8][4];
    #pragma unroll
    for (int i = 0; i < 2; i++)
        #pragma unroll
        for (int j = 0; j < 8; j++)
            #pragma unroll
            for (int r = 0; r < 4; r++) acc[i][j][r] = 0.f;

    gemm_mainloop(ga, acc, wm, wn, lane);

    #pragma unroll
    for (int tm = 0; tm < 2; tm++) {
        #pragma unroll
        for (int tn = 0; tn < 8; tn++) {
            int col = n0 + wn*64 + tn*8 + (lane & 3)*2;
            float b0 = bias[col], b1 = bias[col+1];
            #pragma unroll
            for (int rh = 0; rh < 2; rh++) {
                int row = m0 + wm*32 + tm*16 + (lane >> 2) + rh*8;
                float* dst = C + (size_t)row * CD + col;
                *(float2*)dst = make_float2(acc[tm][tn][rh*2] + b0,
                                            acc[tm][tn][rh*2+1] + b1);
            }
        }
    }
}

// ---------------------------------------------------------------------------
// fp16 tensor-core causal flash attention (mma.sync)
// CTA: (b, h, 64-row q-tile), 128 threads = 4 warps x 16 rows.
// KV tiles of 64, double-buffered. 4 CTAs/SM. Softmax in exp2 domain
// (Q pre-scaled by log2e/8 in projection epilogue).
// ---------------------------------------------------------------------------
#define AT_STRIDE 144
#define AT_QMAT (64*AT_STRIDE)      // 9216
#define AT_KMAT (64*AT_STRIDE)      // 9216
#define AT_STAGE (2*AT_KMAT)        // 18432 (K, V)
#define ATTN_SMEM (AT_QMAT + 2*AT_STAGE)   // 46080

__global__ __launch_bounds__(128, 4)
void attn_tc(const __half* __restrict__ Qg, const __half* __restrict__ Kg,
             const __half* __restrict__ Vg, __half* __restrict__ Og)
{
    extern __shared__ char smem[];
    const uint32_t s0 = smem_u32(smem);
    const int tid = threadIdx.x, w = tid >> 5, lane = tid & 31;

    const int qt = gridDim.x - 1 - blockIdx.x;        // heavy tiles first
    const int h  = blockIdx.y, b = blockIdx.z;
    const size_t g = (size_t)(b * CH + h) * CS * CDK;
    const int q0 = qt * 64;
    const int njt = qt + 1;

    const __half *Q = Qg + g, *K = Kg + g, *V = Vg + g;

    const uint32_t sQ  = s0;
    const uint32_t sKV = s0 + AT_QMAT;

    auto issue_kv = [&](int jt) {
        int kv0 = jt * 64;
        uint32_t sb = sKV + (jt & 1) * AT_STAGE;
        #pragma unroll
        for (int it = 0; it < 4; it++) {       // 64 rows x 8 segs = 512 / 128 thr
            int c = tid + (it << 7);
            int row = c >> 3, seg = c & 7;
            uint32_t so = row * AT_STRIDE + (seg << 4);
            size_t off = (size_t)(kv0 + row) * CDK + (seg << 3);
            cpa16(sb           + so, K + off);
            cpa16(sb + AT_KMAT + so, V + off);
        }
        asm volatile("cp.async.commit_group;" ::: "memory");
    };

    // Q load (64 rows; grouped with kv tile 0)
    #pragma unroll
    for (int it = 0; it < 4; it++) {
        int c = tid + (it << 7);
        int row = c >> 3, seg = c & 7;
        cpa16(sQ + row * AT_STRIDE + (seg << 4), Q + (size_t)(q0 + row) * CDK + (seg << 3));
    }
    issue_kv(0);
    if (njt > 1) issue_kv(1);

    const uint32_t q_off = (w*16 + (lane & 15)) * AT_STRIDE + ((lane >> 4) << 4);
    const uint32_t k_pat = ((lane & 7) + ((lane >> 4) << 3)) * AT_STRIDE + (((lane >> 3) & 1) << 4);
    const uint32_t v_pat = ((lane & 7) + (((lane >> 3) & 1) << 3)) * AT_STRIDE + ((lane >> 4) << 4);

    uint32_t qf[4][4];
    float o[8][4];
    #pragma unroll
    for (int j = 0; j < 8; j++)
        #pragma unroll
        for (int r = 0; r < 4; r++) o[j][r] = 0.f;
    float mA = -1e30f, mB = -1e30f, lA = 0.f, lB = 0.f;

    const int rowA_g = q0 + w*16 + (lane >> 2);
    const int colL   = (lane & 3) * 2;

    for (int jt = 0; jt < njt; jt++) {
        if (jt + 1 < njt) asm volatile("cp.async.wait_group 1;" ::: "memory");
        else              asm volatile("cp.async.wait_group 0;" ::: "memory");
        __syncthreads();

        if (jt == 0) {
            #pragma unroll
            for (int kc = 0; kc < 4; kc++)
                ldsm4(qf[kc], sQ + q_off + kc*32);
        }

        const uint32_t sb = sKV + (jt & 1) * AT_STAGE;
        const int kv0 = jt * 64;

        // ---- S = Q K^T ----
        float s[8][4];
        #pragma unroll
        for (int j = 0; j < 8; j++)
            #pragma unroll
            for (int r = 0; r < 4; r++) s[j][r] = 0.f;

        #pragma unroll
        for (int kc = 0; kc < 4; kc++) {
            uint32_t kfa[4][4];
            ldsm4(kfa[0], sb + k_pat                 + kc*32);
            ldsm4(kfa[1], sb + k_pat + 16*AT_STRIDE  + kc*32);
            ldsm4(kfa[2], sb + k_pat + 32*AT_STRIDE  + kc*32);
            ldsm4(kfa[3], sb + k_pat + 48*AT_STRIDE  + kc*32);
            #pragma unroll
            for (int np = 0; np < 4; np++) {
                mma_f16(s[np*2],   qf[kc], kfa[np]);
                mma_f16(s[np*2+1], qf[kc], kfa[np] + 2);
            }
        }

        // ---- mask (diagonal tile) + online softmax (exp2 domain) ----
        if (jt == qt) {
            #pragma unroll
            for (int tn = 0; tn < 8; tn++) {
                int col = kv0 + tn*8 + colL;
                if (col     > rowA_g) s[tn][0] = -1e30f;
                if (col + 1 > rowA_g) s[tn][1] = -1e30f;
                if (col     > rowA_g + 8) s[tn][2] = -1e30f;
                if (col + 1 > rowA_g + 8) s[tn][3] = -1e30f;
            }
        }

        float mxA = -1e30f, mxB = -1e30f;
        #pragma unroll
        for (int tn = 0; tn < 8; tn++) {
            mxA = fmaxf(mxA, fmaxf(s[tn][0], s[tn][1]));
            mxB = fmaxf(mxB, fmaxf(s[tn][2], s[tn][3]));
        }
        mxA = fmaxf(mxA, __shfl_xor_sync(0xffffffffu, mxA, 1));
        mxA = fmaxf(mxA, __shfl_xor_sync(0xffffffffu, mxA, 2));
        mxB = fmaxf(mxB, __shfl_xor_sync(0xffffffffu, mxB, 1));
        mxB = fmaxf(mxB, __shfl_xor_sync(0xffffffffu, mxB, 2));

        float nmA = fmaxf(mA, mxA), nmB = fmaxf(mB, mxB);
        float facA = ex2(mA - nmA), facB = ex2(mB - nmB);

        float sumA = 0.f, sumB = 0.f;
        #pragma unroll
        for (int tn = 0; tn < 8; tn++) {
            s[tn][0] = ex2(s[tn][0] - nmA);
            s[tn][1] = ex2(s[tn][1] - nmA);
            s[tn][2] = ex2(s[tn][2] - nmB);
            s[tn][3] = ex2(s[tn][3] - nmB);
            sumA += s[tn][0] + s[tn][1];
            sumB += s[tn][2] + s[tn][3];
        }
        sumA += __shfl_xor_sync(0xffffffffu, sumA, 1);
        sumA += __shfl_xor_sync(0xffffffffu, sumA, 2);
        sumB += __shfl_xor_sync(0xffffffffu, sumB, 1);
        sumB += __shfl_xor_sync(0xffffffffu, sumB, 2);

        lA = lA*facA + sumA;  mA = nmA;
        lB = lB*facB + sumB;  mB = nmB;

        #pragma unroll
        for (int tn = 0; tn < 8; tn++) {
            o[tn][0] *= facA; o[tn][1] *= facA;
            o[tn][2] *= facB; o[tn][3] *= facB;
        }

        // ---- O += P V ----
        #pragma unroll
        for (int kc = 0; kc < 4; kc++) {
            uint32_t pa[4];
            pa[0] = packh2(s[2*kc][0],   s[2*kc][1]);
            pa[1] = packh2(s[2*kc][2],   s[2*kc][3]);
            pa[2] = packh2(s[2*kc+1][0], s[2*kc+1][1]);
            pa[3] = packh2(s[2*kc+1][2], s[2*kc+1][3]);
            uint32_t vfa[4][4];
            ldsm4t(vfa[0], sb + AT_KMAT + v_pat + kc*16*AT_STRIDE);
            ldsm4t(vfa[1], sb + AT_KMAT + v_pat + kc*16*AT_STRIDE + 32);
            ldsm4t(vfa[2], sb + AT_KMAT + v_pat + kc*16*AT_STRIDE + 64);
            ldsm4t(vfa[3], sb + AT_KMAT + v_pat + kc*16*AT_STRIDE + 96);
            #pragma unroll
            for (int np = 0; np < 4; np++) {
                mma_f16(o[np*2],   pa, vfa[np]);
                mma_f16(o[np*2+1], pa, vfa[np] + 2);
            }
        }

        __syncthreads();
        if (jt + 2 < njt) issue_kv(jt + 2);
    }

    // ---- epilogue: normalize, fp16 store to [B,S,D] ----
    float invA = 1.f / lA, invB = 1.f / lB;
    #pragma unroll
    for (int tn = 0; tn < 8; tn++) {
        int col = h*CDK + tn*8 + colL;
        #pragma unroll
        for (int rh = 0; rh < 2; rh++) {
            int q = q0 + w*16 + (lane >> 2) + rh*8;
            float inv = rh ? invB : invA;
            size_t idx = (size_t)(b*CS + q) * CD + col;
            *(__half2*)(Og + idx) = __floats2half2_rn(o[tn][rh*2] * inv,
                                                      o[tn][rh*2+1] * inv);
        }
    }
}

// ---------------------------------------------------------------------------
extern "C" void kernel_launch(void* const* d_in, const int* in_sizes, int n_in,
                              void* d_out, int out_size)
{
    const float* x  = (const float*)d_in[0];
    // d_in[1] = mask (causal triu(k=1), handled analytically)
    const float* Wq = (const float*)d_in[2];
    const float* bq = (const float*)d_in[3];
    const float* Wk = (const float*)d_in[4];
    const float* bk = (const float*)d_in[5];
    const float* Wv = (const float*)d_in[6];
    const float* bv = (const float*)d_in[7];
    const float* Wo = (const float*)d_in[8];
    const float* bo = (const float*)d_in[9];
    float* out = (float*)d_out;

    __half *x16, *w16, *q16, *k16, *v16, *a16;
    cudaGetSymbolAddress((void**)&x16, g_x16);
    cudaGetSymbolAddress((void**)&w16, g_w16);
    cudaGetSymbolAddress((void**)&q16, g_q16);
    cudaGetSymbolAddress((void**)&k16, g_k16);
    cudaGetSymbolAddress((void**)&v16, g_v16);
    cudaGetSymbolAddress((void**)&a16, g_a16);

    // One-time host resources (exist before the harness's capture pass;
    // device work per call is identical and deterministic).
    static cudaStream_t s1 = nullptr, s2 = nullptr;
    static cudaEvent_t eRoot = nullptr, e1 = nullptr, e2 = nullptr;
    static bool configured = false;
    if (!configured) {
        cudaStreamCreateWithFlags(&s1, cudaStreamNonBlocking);
        cudaStreamCreateWithFlags(&s2, cudaStreamNonBlocking);
        cudaEventCreateWithFlags(&eRoot, cudaEventDisableTiming);
        cudaEventCreateWithFlags(&e1, cudaEventDisableTiming);
        cudaEventCreateWithFlags(&e2, cudaEventDisableTiming);
        cudaFuncSetAttribute(attn_tc,  cudaFuncAttributeMaxDynamicSharedMemorySize, ATTN_SMEM);
        cudaFuncSetAttribute(gemm_qkv, cudaFuncAttributeMaxDynamicSharedMemorySize, GEMM_SMEM);
        cudaFuncSetAttribute(gemm_o,   cudaFuncAttributeMaxDynamicSharedMemorySize, GEMM_SMEM);
        configured = true;
    }

    // Fork: trig on s1, wcvt on s2, cvt on the main (capture) stream.
    cudaEventRecord(eRoot, 0);
    cudaStreamWaitEvent(s1, eRoot, 0);
    cudaStreamWaitEvent(s2, eRoot, 0);

    trig_kernel<<<256, 256, 0, s1>>>();
    wcvt_kernel<<<dim3(32,32,4), 256, 0, s2>>>(Wq, Wk, Wv, Wo, w16);
    cvt_kernel<<<(CM*CD)/1024, 256>>>(x, x16);

    cudaEventRecord(e1, s1);
    cudaEventRecord(e2, s2);
    cudaStreamWaitEvent(0, e1, 0);
    cudaStreamWaitEvent(0, e2, 0);

    // Join: main pipeline on the capture stream.
    gemm_qkv<<<dim3(CD/128, CM/128, 3), 256, GEMM_SMEM>>>(
        x16, w16, bq, bk, bv, q16, k16, v16);

    attn_tc<<<dim3(CS/64, CH, CB), 128, ATTN_SMEM>>>(q16, k16, v16, a16);

    gemm_o<<<dim3(CD/128, CM/128), 256, GEMM_SMEM>>>(
        a16, w16 + 3*(size_t)CD*CD, bo, out);
}

// round 15
// speedup vs baseline: 1.1117x; 1.0095x over previous
#include <cuda_runtime.h>
#include <cuda_fp16.h>
#include <math.h>
#include <stdint.h>

#define CB 2
#define CS 2048
#define CD 1024
#define CH 16
#define CDK 64
#define CM (CB*CS)   // 4096

// ---------------------------------------------------------------------------
// Scratch (__device__ globals; allocation-free rule)
// ---------------------------------------------------------------------------
__device__ float g_trig[CS*32*2];
__device__ __half g_x16[CM*CD];
__device__ __half g_w16[4][CD*CD];          // W^T fp16 (q,k,v,o)
__device__ __half g_q16[CB*CH*CS*CDK];
__device__ __half g_k16[CB*CH*CS*CDK];
__device__ __half g_v16[CB*CH*CS*CDK];
__device__ __half g_a16[CM*CD];             // attn out fp16

// ---------------------------------------------------------------------------
// Helpers
// ---------------------------------------------------------------------------
__device__ __forceinline__ uint32_t smem_u32(const void* p) {
    uint32_t a;
    asm("{ .reg .u64 t; cvta.to.shared.u64 t, %1; cvt.u32.u64 %0, t; }" : "=r"(a) : "l"(p));
    return a;
}

__device__ __forceinline__ float ex2(float x)
{
    float r;
    asm("ex2.approx.f32 %0, %1;" : "=f"(r) : "f"(x));
    return r;
}

__device__ __forceinline__ void cpa16(uint32_t s, const void* g)
{
    asm volatile("cp.async.cg.shared.global [%0], [%1], 16;"
                 :: "r"(s), "l"(__cvta_generic_to_global(g)) : "memory");
}

__device__ __forceinline__ void ldsm4(uint32_t* r, uint32_t addr)
{
    asm volatile("ldmatrix.sync.aligned.m8n8.x4.shared.b16 {%0,%1,%2,%3}, [%4];"
                 : "=r"(r[0]), "=r"(r[1]), "=r"(r[2]), "=r"(r[3]) : "r"(addr));
}

__device__ __forceinline__ void ldsm4t(uint32_t* r, uint32_t addr)
{
    asm volatile("ldmatrix.sync.aligned.m8n8.x4.trans.shared.b16 {%0,%1,%2,%3}, [%4];"
                 : "=r"(r[0]), "=r"(r[1]), "=r"(r[2]), "=r"(r[3]) : "r"(addr));
}

__device__ __forceinline__ void mma_f16(float* c, const uint32_t* a, const uint32_t* b)
{
    asm volatile("mma.sync.aligned.m16n8k16.row.col.f32.f16.f16.f32 "
                 "{%0,%1,%2,%3}, {%4,%5,%6,%7}, {%8,%9}, {%0,%1,%2,%3};"
                 : "+f"(c[0]), "+f"(c[1]), "+f"(c[2]), "+f"(c[3])
                 : "r"(a[0]), "r"(a[1]), "r"(a[2]), "r"(a[3]), "r"(b[0]), "r"(b[1]));
}

__device__ __forceinline__ uint32_t packh2(float a, float b)
{
    __half2 t = __floats2half2_rn(a, b);
    return *(uint32_t*)&t;
}

// ---------------------------------------------------------------------------
// Prep kernels
// ---------------------------------------------------------------------------
__global__ void trig_kernel()
{
    int t = blockIdx.x * 256 + threadIdx.x;
    int s = t >> 5, i = t & 31;
    double theta = exp((double)i * (-log(10000.0) / 32.0));
    double a = (double)s * theta;
    g_trig[t*2]   = (float)cos(a);
    g_trig[t*2+1] = (float)sin(a);
}

__global__ void cvt_kernel(const float* __restrict__ src, __half* __restrict__ dst)
{
    int i = (blockIdx.x * 256 + threadIdx.x) * 4;
    float4 v = *(const float4*)(src + i);
    *(__half2*)(dst + i)     = __floats2half2_rn(v.x, v.y);
    *(__half2*)(dst + i + 2) = __floats2half2_rn(v.z, v.w);
}

// W[k][n] -> out[n][k] transposed fp16; z selects which of 4 weights
__global__ void wcvt_kernel(const float* __restrict__ W0, const float* __restrict__ W1,
                            const float* __restrict__ W2, const float* __restrict__ W3,
                            __half* __restrict__ out)
{
    __shared__ float t[32][33];
    const int z = blockIdx.z;
    const float* W = (z == 0) ? W0 : (z == 1) ? W1 : (z == 2) ? W2 : W3;
    __half* dst = out + (size_t)z * CD * CD;
    int bx = blockIdx.x * 32, by = blockIdx.y * 32;
    int tx = threadIdx.x & 31, ty = threadIdx.x >> 5;
    #pragma unroll
    for (int i = 0; i < 4; i++)
        t[ty + 8*i][tx] = W[(size_t)(by + ty + 8*i) * CD + bx + tx];
    __syncthreads();
    #pragma unroll
    for (int i = 0; i < 4; i++) {
        float x = t[tx][ty + 8*i];    // = W[by+tx][bx+ty+8i]
        dst[(size_t)(bx + ty + 8*i) * CD + by + tx] = __float2half_rn(x);
    }
}

// ---------------------------------------------------------------------------
// fp16 tensor-core GEMM: C[4096,1024] = A[M,K] @ B[N,K]^T + bias  (R9 proven)
// ---------------------------------------------------------------------------
#define ASTRIDE 144
#define MATB (128*144)          // 18432
#define BUFB (2*MATB)           // A, B
#define NSTAGE 2
#define GEMM_SMEM (NSTAGE*BUFB) // 73728

struct GArgs {
    const __half *A, *B;
    int m0, n0, tid;
    uint32_t s0;
};

__device__ __forceinline__ void issue_chunk(const GArgs& a, int chunk)
{
    int k0 = chunk << 6;
    uint32_t base = a.s0 + (chunk & 1) * BUFB;
    #pragma unroll
    for (int it = 0; it < 4; it++) {
        int c = a.tid + (it << 8);
        int row = c >> 3, seg = c & 7;
        uint32_t so = row * ASTRIDE + (seg << 4);
        cpa16(base        + so, a.A + (size_t)(a.m0 + row) * CD + k0 + (seg << 3));
        cpa16(base + MATB + so, a.B + (size_t)(a.n0 + row) * CD + k0 + (seg << 3));
    }
    asm volatile("cp.async.commit_group;" ::: "memory");
}

__device__ __forceinline__ void gemm_mainloop(const GArgs& ga, float acc[2][8][4],
                                              int wm, int wn, int lane)
{
    issue_chunk(ga, 0);

    const uint32_t a_off = (wm*32 + (lane & 15)) * ASTRIDE + ((lane >> 4) << 4);
    const uint32_t b_off = MATB +
        (wn*64 + (lane & 7) + ((lane >> 4) << 3)) * ASTRIDE + (((lane >> 3) & 1) << 4);

    for (int i = 0; i < 16; i++) {
        if (i + 1 < 16) {
            issue_chunk(ga, i + 1);
            asm volatile("cp.async.wait_group 1;" ::: "memory");
        } else {
            asm volatile("cp.async.wait_group 0;" ::: "memory");
        }
        __syncthreads();

        uint32_t buf = ga.s0 + (i & 1) * BUFB;
        #pragma unroll
        for (int ks = 0; ks < 4; ks++) {
            uint32_t af[2][4], bfa[4][4];
            ldsm4(af[0], buf + a_off + ks*32);
            ldsm4(af[1], buf + a_off + 16*ASTRIDE + ks*32);
            ldsm4(bfa[0], buf + b_off                 + ks*32);
            ldsm4(bfa[1], buf + b_off + 16*ASTRIDE    + ks*32);
            ldsm4(bfa[2], buf + b_off + 32*ASTRIDE    + ks*32);
            ldsm4(bfa[3], buf + b_off + 48*ASTRIDE    + ks*32);
            #pragma unroll
            for (int tp = 0; tp < 4; tp++) {
                #pragma unroll
                for (int half = 0; half < 2; half++) {
                    int tn = tp*2 + half;
                    mma_f16(acc[0][tn], af[0], bfa[tp] + half*2);
                    mma_f16(acc[1][tn], af[1], bfa[tp] + half*2);
                }
            }
        }
        __syncthreads();
    }
}

// QKV fused (m_base selects batch half); epilogue: bias, rope (q,k),
// q-prescale log2e/8, fp16 scatter [B,H,S,DK]
__global__ __launch_bounds__(256, 2)
void gemm_qkv(const __half* __restrict__ A, const __half* __restrict__ W16,
              const float* __restrict__ bq, const float* __restrict__ bk,
              const float* __restrict__ bv,
              __half* __restrict__ Q, __half* __restrict__ K, __half* __restrict__ V,
              int m_base)
{
    extern __shared__ char smem[];
    const uint32_t s0 = smem_u32(smem);
    const int tid = threadIdx.x, wid = tid >> 5, lane = tid & 31;
    const int wm = wid & 3, wn = wid >> 2;
    const int m0 = m_base + (blockIdx.y << 7), n0 = blockIdx.x << 7;
    const int z  = blockIdx.z;

    const __half* B = W16 + (size_t)z * CD * CD;
    const float* bias = (z == 0) ? bq : (z == 1) ? bk : bv;
    __half* D = (z == 0) ? Q : (z == 1) ? K : V;
    const bool rope = (z < 2);
    const float oscale = (z == 0) ? 0.18033688011112042f : 1.0f;

    GArgs ga{A, B, m0, n0, tid, s0};

    float acc[2][8][4];
    #pragma unroll
    for (int i = 0; i < 2; i++)
        #pragma unroll
        for (int j = 0; j < 8; j++)
            #pragma unroll
            for (int r = 0; r < 4; r++) acc[i][j][r] = 0.f;

    gemm_mainloop(ga, acc, wm, wn, lane);

    #pragma unroll
    for (int tm = 0; tm < 2; tm++) {
        #pragma unroll
        for (int tn = 0; tn < 8; tn++) {
            int col = n0 + wn*64 + tn*8 + (lane & 3)*2;
            float b0 = bias[col], b1 = bias[col+1];
            acc[tm][tn][0] += b0; acc[tm][tn][1] += b1;
            acc[tm][tn][2] += b0; acc[tm][tn][3] += b1;
        }
    }

    if (rope) {
        #pragma unroll
        for (int tm = 0; tm < 2; tm++) {
            #pragma unroll
            for (int tn = 0; tn < 4; tn++) {
                #pragma unroll
                for (int r = 0; r < 4; r++) {
                    int row = m0 + wm*32 + tm*16 + (lane >> 2) + (r >> 1)*8;
                    int s   = row & (CS - 1);
                    int p   = tn*8 + (lane & 3)*2 + (r & 1);
                    float cc = g_trig[(s*32 + p)*2];
                    float sn = g_trig[(s*32 + p)*2 + 1];
                    float lo = acc[tm][tn][r], hi = acc[tm][tn+4][r];
                    acc[tm][tn][r]   = lo*cc - hi*sn;
                    acc[tm][tn+4][r] = hi*cc + lo*sn;
                }
            }
        }
    }

    #pragma unroll
    for (int tm = 0; tm < 2; tm++) {
        #pragma unroll
        for (int tn = 0; tn < 8; tn++) {
            int col = n0 + wn*64 + tn*8 + (lane & 3)*2;
            int h_ = col >> 6, dk = col & 63;
            #pragma unroll
            for (int rh = 0; rh < 2; rh++) {
                int row = m0 + wm*32 + tm*16 + (lane >> 2) + rh*8;
                int b_ = row >> 11, s_ = row & (CS - 1);
                size_t idx = ((size_t)((b_*CH + h_)*CS + s_)) * CDK + dk;
                *(__half2*)(D + idx) = __floats2half2_rn(acc[tm][tn][rh*2]   * oscale,
                                                         acc[tm][tn][rh*2+1] * oscale);
            }
        }
    }
}

// Output projection: row-major fp32 C (m_base selects batch half).
__global__ __launch_bounds__(256, 2)
void gemm_o(const __half* __restrict__ A, const __half* __restrict__ B,
            const float* __restrict__ bias, float* __restrict__ C, int m_base)
{
    extern __shared__ char smem[];
    const uint32_t s0 = smem_u32(smem);
    const int tid = threadIdx.x, wid = tid >> 5, lane = tid & 31;
    const int wm = wid & 3, wn = wid >> 2;
    const int m0 = m_base + (blockIdx.y << 7), n0 = blockIdx.x << 7;

    GArgs ga{A, B, m0, n0, tid, s0};

    float acc[2][8][4];
    #pragma unroll
    for (int i = 0; i < 2; i++)
        #pragma unroll
        for (int j = 0; j < 8; j++)
            #pragma unroll
            for (int r = 0; r < 4; r++) acc[i][j][r] = 0.f;

    gemm_mainloop(ga, acc, wm, wn, lane);

    #pragma unroll
    for (int tm = 0; tm < 2; tm++) {
        #pragma unroll
        for (int tn = 0; tn < 8; tn++) {
            int col = n0 + wn*64 + tn*8 + (lane & 3)*2;
            float b0 = bias[col], b1 = bias[col+1];
            #pragma unroll
            for (int rh = 0; rh < 2; rh++) {
                int row = m0 + wm*32 + tm*16 + (lane >> 2) + rh*8;
                float* dst = C + (size_t)row * CD + col;
                *(float2*)dst = make_float2(acc[tm][tn][rh*2] + b0,
                                            acc[tm][tn][rh*2+1] + b1);
            }
        }
    }
}

// ---------------------------------------------------------------------------
// fp16 tensor-core causal flash attention (mma.sync), single batch (b_fix).
// CTA: (h, 64-row q-tile), 128 threads = 4 warps x 16 rows.
// KV tiles of 64, double-buffered. 4 CTAs/SM. Softmax in exp2 domain.
// ---------------------------------------------------------------------------
#define AT_STRIDE 144
#define AT_QMAT (64*AT_STRIDE)      // 9216
#define AT_KMAT (64*AT_STRIDE)      // 9216
#define AT_STAGE (2*AT_KMAT)        // 18432 (K, V)
#define ATTN_SMEM (AT_QMAT + 2*AT_STAGE)   // 46080

__global__ __launch_bounds__(128, 4)
void attn_tc(const __half* __restrict__ Qg, const __half* __restrict__ Kg,
             const __half* __restrict__ Vg, __half* __restrict__ Og, int b_fix)
{
    extern __shared__ char smem[];
    const uint32_t s0 = smem_u32(smem);
    const int tid = threadIdx.x, w = tid >> 5, lane = tid & 31;

    const int qt = gridDim.x - 1 - blockIdx.x;        // heavy tiles first
    const int h  = blockIdx.y, b = b_fix;
    const size_t g = (size_t)(b * CH + h) * CS * CDK;
    const int q0 = qt * 64;
    const int njt = qt + 1;

    const __half *Q = Qg + g, *K = Kg + g, *V = Vg + g;

    const uint32_t sQ  = s0;
    const uint32_t sKV = s0 + AT_QMAT;

    auto issue_kv = [&](int jt) {
        int kv0 = jt * 64;
        uint32_t sb = sKV + (jt & 1) * AT_STAGE;
        #pragma unroll
        for (int it = 0; it < 4; it++) {
            int c = tid + (it << 7);
            int row = c >> 3, seg = c & 7;
            uint32_t so = row * AT_STRIDE + (seg << 4);
            size_t off = (size_t)(kv0 + row) * CDK + (seg << 3);
            cpa16(sb           + so, K + off);
            cpa16(sb + AT_KMAT + so, V + off);
        }
        asm volatile("cp.async.commit_group;" ::: "memory");
    };

    #pragma unroll
    for (int it = 0; it < 4; it++) {
        int c = tid + (it << 7);
        int row = c >> 3, seg = c & 7;
        cpa16(sQ + row * AT_STRIDE + (seg << 4), Q + (size_t)(q0 + row) * CDK + (seg << 3));
    }
    issue_kv(0);
    if (njt > 1) issue_kv(1);

    const uint32_t q_off = (w*16 + (lane & 15)) * AT_STRIDE + ((lane >> 4) << 4);
    const uint32_t k_pat = ((lane & 7) + ((lane >> 4) << 3)) * AT_STRIDE + (((lane >> 3) & 1) << 4);
    const uint32_t v_pat = ((lane & 7) + (((lane >> 3) & 1) << 3)) * AT_STRIDE + ((lane >> 4) << 4);

    uint32_t qf[4][4];
    float o[8][4];
    #pragma unroll
    for (int j = 0; j < 8; j++)
        #pragma unroll
        for (int r = 0; r < 4; r++) o[j][r] = 0.f;
    float mA = -1e30f, mB = -1e30f, lA = 0.f, lB = 0.f;

    const int rowA_g = q0 + w*16 + (lane >> 2);
    const int colL   = (lane & 3) * 2;

    for (int jt = 0; jt < njt; jt++) {
        if (jt + 1 < njt) asm volatile("cp.async.wait_group 1;" ::: "memory");
        else              asm volatile("cp.async.wait_group 0;" ::: "memory");
        __syncthreads();

        if (jt == 0) {
            #pragma unroll
            for (int kc = 0; kc < 4; kc++)
                ldsm4(qf[kc], sQ + q_off + kc*32);
        }

        const uint32_t sb = sKV + (jt & 1) * AT_STAGE;
        const int kv0 = jt * 64;

        float s[8][4];
        #pragma unroll
        for (int j = 0; j < 8; j++)
            #pragma unroll
            for (int r = 0; r < 4; r++) s[j][r] = 0.f;

        #pragma unroll
        for (int kc = 0; kc < 4; kc++) {
            uint32_t kfa[4][4];
            ldsm4(kfa[0], sb + k_pat                 + kc*32);
            ldsm4(kfa[1], sb + k_pat + 16*AT_STRIDE  + kc*32);
            ldsm4(kfa[2], sb + k_pat + 32*AT_STRIDE  + kc*32);
            ldsm4(kfa[3], sb + k_pat + 48*AT_STRIDE  + kc*32);
            #pragma unroll
            for (int np = 0; np < 4; np++) {
                mma_f16(s[np*2],   qf[kc], kfa[np]);
                mma_f16(s[np*2+1], qf[kc], kfa[np] + 2);
            }
        }

        if (jt == qt) {
            #pragma unroll
            for (int tn = 0; tn < 8; tn++) {
                int col = kv0 + tn*8 + colL;
                if (col     > rowA_g) s[tn][0] = -1e30f;
                if (col + 1 > rowA_g) s[tn][1] = -1e30f;
                if (col     > rowA_g + 8) s[tn][2] = -1e30f;
                if (col + 1 > rowA_g + 8) s[tn][3] = -1e30f;
            }
        }

        float mxA = -1e30f, mxB = -1e30f;
        #pragma unroll
        for (int tn = 0; tn < 8; tn++) {
            mxA = fmaxf(mxA, fmaxf(s[tn][0], s[tn][1]));
            mxB = fmaxf(mxB, fmaxf(s[tn][2], s[tn][3]));
        }
        mxA = fmaxf(mxA, __shfl_xor_sync(0xffffffffu, mxA, 1));
        mxA = fmaxf(mxA, __shfl_xor_sync(0xffffffffu, mxA, 2));
        mxB = fmaxf(mxB, __shfl_xor_sync(0xffffffffu, mxB, 1));
        mxB = fmaxf(mxB, __shfl_xor_sync(0xffffffffu, mxB, 2));

        float nmA = fmaxf(mA, mxA), nmB = fmaxf(mB, mxB);
        float facA = ex2(mA - nmA), facB = ex2(mB - nmB);

        float sumA = 0.f, sumB = 0.f;
        #pragma unroll
        for (int tn = 0; tn < 8; tn++) {
            s[tn][0] = ex2(s[tn][0] - nmA);
            s[tn][1] = ex2(s[tn][1] - nmA);
            s[tn][2] = ex2(s[tn][2] - nmB);
            s[tn][3] = ex2(s[tn][3] - nmB);
            sumA += s[tn][0] + s[tn][1];
            sumB += s[tn][2] + s[tn][3];
        }
        sumA += __shfl_xor_sync(0xffffffffu, sumA, 1);
        sumA += __shfl_xor_sync(0xffffffffu, sumA, 2);
        sumB += __shfl_xor_sync(0xffffffffu, sumB, 1);
        sumB += __shfl_xor_sync(0xffffffffu, sumB, 2);

        lA = lA*facA + sumA;  mA = nmA;
        lB = lB*facB + sumB;  mB = nmB;

        #pragma unroll
        for (int tn = 0; tn < 8; tn++) {
            o[tn][0] *= facA; o[tn][1] *= facA;
            o[tn][2] *= facB; o[tn][3] *= facB;
        }

        #pragma unroll
        for (int kc = 0; kc < 4; kc++) {
            uint32_t pa[4];
            pa[0] = packh2(s[2*kc][0],   s[2*kc][1]);
            pa[1] = packh2(s[2*kc][2],   s[2*kc][3]);
            pa[2] = packh2(s[2*kc+1][0], s[2*kc+1][1]);
            pa[3] = packh2(s[2*kc+1][2], s[2*kc+1][3]);
            uint32_t vfa[4][4];
            ldsm4t(vfa[0], sb + AT_KMAT + v_pat + kc*16*AT_STRIDE);
            ldsm4t(vfa[1], sb + AT_KMAT + v_pat + kc*16*AT_STRIDE + 32);
            ldsm4t(vfa[2], sb + AT_KMAT + v_pat + kc*16*AT_STRIDE + 64);
            ldsm4t(vfa[3], sb + AT_KMAT + v_pat + kc*16*AT_STRIDE + 96);
            #pragma unroll
            for (int np = 0; np < 4; np++) {
                mma_f16(o[np*2],   pa, vfa[np]);
                mma_f16(o[np*2+1], pa, vfa[np] + 2);
            }
        }

        __syncthreads();
        if (jt + 2 < njt) issue_kv(jt + 2);
    }

    float invA = 1.f / lA, invB = 1.f / lB;
    #pragma unroll
    for (int tn = 0; tn < 8; tn++) {
        int col = h*CDK + tn*8 + colL;
        #pragma unroll
        for (int rh = 0; rh < 2; rh++) {
            int q = q0 + w*16 + (lane >> 2) + rh*8;
            float inv = rh ? invB : invA;
            size_t idx = (size_t)(b*CS + q) * CD + col;
            *(__half2*)(Og + idx) = __floats2half2_rn(o[tn][rh*2] * inv,
                                                      o[tn][rh*2+1] * inv);
        }
    }
}

// ---------------------------------------------------------------------------
extern "C" void kernel_launch(void* const* d_in, const int* in_sizes, int n_in,
                              void* d_out, int out_size)
{
    const float* x  = (const float*)d_in[0];
    // d_in[1] = mask (causal triu(k=1), handled analytically)
    const float* Wq = (const float*)d_in[2];
    const float* bq = (const float*)d_in[3];
    const float* Wk = (const float*)d_in[4];
    const float* bk = (const float*)d_in[5];
    const float* Wv = (const float*)d_in[6];
    const float* bv = (const float*)d_in[7];
    const float* Wo = (const float*)d_in[8];
    const float* bo = (const float*)d_in[9];
    float* out = (float*)d_out;

    __half *x16, *w16, *q16, *k16, *v16, *a16;
    cudaGetSymbolAddress((void**)&x16, g_x16);
    cudaGetSymbolAddress((void**)&w16, g_w16);
    cudaGetSymbolAddress((void**)&q16, g_q16);
    cudaGetSymbolAddress((void**)&k16, g_k16);
    cudaGetSymbolAddress((void**)&v16, g_v16);
    cudaGetSymbolAddress((void**)&a16, g_a16);

    static cudaStream_t s1 = nullptr, s2 = nullptr;
    static cudaEvent_t eRoot = nullptr, e1 = nullptr, e2 = nullptr;
    static cudaEvent_t eQ0 = nullptr, eJ = nullptr;
    static bool configured = false;
    if (!configured) {
        cudaStreamCreateWithFlags(&s1, cudaStreamNonBlocking);
        cudaStreamCreateWithFlags(&s2, cudaStreamNonBlocking);
        cudaEventCreateWithFlags(&eRoot, cudaEventDisableTiming);
        cudaEventCreateWithFlags(&e1, cudaEventDisableTiming);
        cudaEventCreateWithFlags(&e2, cudaEventDisableTiming);
        cudaEventCreateWithFlags(&eQ0, cudaEventDisableTiming);
        cudaEventCreateWithFlags(&eJ, cudaEventDisableTiming);
        cudaFuncSetAttribute(attn_tc,  cudaFuncAttributeMaxDynamicSharedMemorySize, ATTN_SMEM);
        cudaFuncSetAttribute(gemm_qkv, cudaFuncAttributeMaxDynamicSharedMemorySize, GEMM_SMEM);
        cudaFuncSetAttribute(gemm_o,   cudaFuncAttributeMaxDynamicSharedMemorySize, GEMM_SMEM);
        configured = true;
    }

    // ---- Prep fork: trig on s1, wcvt on s2, cvt on main ----
    cudaEventRecord(eRoot, 0);
    cudaStreamWaitEvent(s1, eRoot, 0);
    cudaStreamWaitEvent(s2, eRoot, 0);

    trig_kernel<<<256, 256, 0, s1>>>();
    wcvt_kernel<<<dim3(32,32,4), 256, 0, s2>>>(Wq, Wk, Wv, Wo, w16);
    cvt_kernel<<<(CM*CD)/1024, 256>>>(x, x16);

    cudaEventRecord(e1, s1);
    cudaEventRecord(e2, s2);
    cudaStreamWaitEvent(0, e1, 0);
    cudaStreamWaitEvent(0, e2, 0);

    // ---- Batch-pipelined main flow ----
    // main: qkv(b0) -> [eQ0] -> qkv(b1) -> attn(b1) -> gemm_o(b1)
    // s1:   wait eQ0 -> attn(b0) -> gemm_o(b0) -> [eJ]
    gemm_qkv<<<dim3(CD/128, 16, 3), 256, GEMM_SMEM>>>(
        x16, w16, bq, bk, bv, q16, k16, v16, 0);
    cudaEventRecord(eQ0, 0);

    gemm_qkv<<<dim3(CD/128, 16, 3), 256, GEMM_SMEM>>>(
        x16, w16, bq, bk, bv, q16, k16, v16, 2048);

    cudaStreamWaitEvent(s1, eQ0, 0);
    attn_tc<<<dim3(CS/64, CH, 1), 128, ATTN_SMEM, s1>>>(q16, k16, v16, a16, 0);
    gemm_o<<<dim3(CD/128, 16), 256, GEMM_SMEM, s1>>>(
        a16, w16 + 3*(size_t)CD*CD, bo, out, 0);
    cudaEventRecord(eJ, s1);

    attn_tc<<<dim3(CS/64, CH, 1), 128, ATTN_SMEM>>>(q16, k16, v16, a16, 1);
    gemm_o<<<dim3(CD/128, 16), 256, GEMM_SMEM>>>(
        a16, w16 + 3*(size_t)CD*CD, bo, out, 2048);

    cudaStreamWaitEvent(0, eJ, 0);
}